// round 1
// baseline (speedup 1.0000x reference)
#include <cuda_runtime.h>
#include <cuda_bf16.h>
#include <math.h>

// Problem constants
#define B_      2
#define S_      2048
#define DMODEL  2048
#define NQH     32
#define NKVH    8
#define HD      64
#define KVDIM   (NKVH * HD)   // 512

// Scratch buffers (allocation-free rule: __device__ globals)
__device__ float g_Q[B_ * S_ * DMODEL];   // 32 MB
__device__ float g_K[B_ * S_ * KVDIM];    //  8 MB
__device__ float g_V[B_ * S_ * KVDIM];    //  8 MB
__device__ float g_A[B_ * S_ * DMODEL];   // 32 MB (attention output, [b,s,h,hd])

// ---------------------------------------------------------------------------
// SGEMM: C[M,N] = A[M,K] * B[N,K]^T   (both row-major, nn.Linear convention)
// 64x64 block tile, BK=16, 256 threads, 4x4 per-thread micro-tile.
// ---------------------------------------------------------------------------
#define BM 64
#define BN 64
#define BK 16

__global__ void __launch_bounds__(256) sgemm_abt(
    const float* __restrict__ A, const float* __restrict__ Bm,
    float* __restrict__ C, int M, int N, int K)
{
    __shared__ float As[BK][BM];
    __shared__ float Bs[BK][BN];

    const int tid = threadIdx.x;
    const int tx = tid % 16;          // 0..15 -> N
    const int ty = tid / 16;          // 0..15 -> M
    const int bm = blockIdx.y * BM;
    const int bn = blockIdx.x * BN;

    // cooperative-load mapping: 64 rows x 16 cols, float4 per thread
    const int lrow = tid / 4;         // 0..63
    const int lcol = (tid % 4) * 4;   // 0,4,8,12

    float acc[4][4];
    #pragma unroll
    for (int i = 0; i < 4; i++)
        #pragma unroll
        for (int j = 0; j < 4; j++) acc[i][j] = 0.0f;

    for (int k0 = 0; k0 < K; k0 += BK) {
        float4 a = *(const float4*)(A + (size_t)(bm + lrow) * K + k0 + lcol);
        float4 b = *(const float4*)(Bm + (size_t)(bn + lrow) * K + k0 + lcol);
        As[lcol + 0][lrow] = a.x; As[lcol + 1][lrow] = a.y;
        As[lcol + 2][lrow] = a.z; As[lcol + 3][lrow] = a.w;
        Bs[lcol + 0][lrow] = b.x; Bs[lcol + 1][lrow] = b.y;
        Bs[lcol + 2][lrow] = b.z; Bs[lcol + 3][lrow] = b.w;
        __syncthreads();

        #pragma unroll
        for (int kk = 0; kk < BK; kk++) {
            float ar[4], br[4];
            #pragma unroll
            for (int i = 0; i < 4; i++) ar[i] = As[kk][ty * 4 + i];
            #pragma unroll
            for (int j = 0; j < 4; j++) br[j] = Bs[kk][tx * 4 + j];
            #pragma unroll
            for (int i = 0; i < 4; i++)
                #pragma unroll
                for (int j = 0; j < 4; j++)
                    acc[i][j] = fmaf(ar[i], br[j], acc[i][j]);
        }
        __syncthreads();
    }

    #pragma unroll
    for (int i = 0; i < 4; i++) {
        const int row = bm + ty * 4 + i;
        #pragma unroll
        for (int j = 0; j < 4; j++) {
            C[(size_t)row * N + bn + tx * 4 + j] = acc[i][j];
        }
    }
}

// ---------------------------------------------------------------------------
// Flash-style attention (fp32, online softmax).
// grid: (S/128, NQH, B), 128 threads; thread t owns q-row blockIdx.x*128 + t.
// K/V tiles of 64 rows staged in smem; all threads read K row j in lockstep
// (smem broadcast, conflict-free).
// ---------------------------------------------------------------------------
__global__ void __launch_bounds__(128) flash_attn(
    const float* __restrict__ Q, const float* __restrict__ K,
    const float* __restrict__ V, float* __restrict__ O)
{
    __shared__ float Ks[64][HD];
    __shared__ float Vs[64][HD];

    const int b = blockIdx.z;
    const int h = blockIdx.y;
    const int row = blockIdx.x * 128 + threadIdx.x;   // q position in sequence
    const int kvh = h / (NQH / NKVH);                 // h / 4

    const float* qptr = Q + ((size_t)(b * S_ + row) * DMODEL) + h * HD;
    const float* kbase = K + (size_t)b * S_ * KVDIM + kvh * HD;
    const float* vbase = V + (size_t)b * S_ * KVDIM + kvh * HD;

    float q[HD];
    #pragma unroll
    for (int d = 0; d < HD; d++) q[d] = qptr[d] * 0.125f;  // 1/sqrt(64)

    float out[HD];
    #pragma unroll
    for (int d = 0; d < HD; d++) out[d] = 0.0f;
    float m = -1e30f, l = 0.0f;

    for (int t = 0; t < S_; t += 64) {
        // stage 64x64 K and V tiles (128 threads, float4)
        for (int i = threadIdx.x; i < 64 * 16; i += 128) {
            const int r = i / 16;
            const int c = (i % 16) * 4;
            *(float4*)&Ks[r][c] = *(const float4*)(kbase + (size_t)(t + r) * KVDIM + c);
            *(float4*)&Vs[r][c] = *(const float4*)(vbase + (size_t)(t + r) * KVDIM + c);
        }
        __syncthreads();

        for (int j = 0; j < 64; j++) {
            float s = 0.0f;
            #pragma unroll
            for (int d = 0; d < HD; d++) s = fmaf(q[d], Ks[j][d], s);
            if (s > m) {                     // rare (~log(S) times per row)
                const float c = __expf(m - s);
                l *= c;
                #pragma unroll
                for (int d = 0; d < HD; d++) out[d] *= c;
                m = s;
            }
            const float p = __expf(s - m);
            l += p;
            #pragma unroll
            for (int d = 0; d < HD; d++) out[d] = fmaf(p, Vs[j][d], out[d]);
        }
        __syncthreads();
    }

    const float inv = 1.0f / l;
    float* optr = O + ((size_t)(b * S_ + row) * DMODEL) + h * HD;
    #pragma unroll
    for (int d = 0; d < HD; d++) optr[d] = out[d] * inv;
}

// ---------------------------------------------------------------------------
// Launch
// ---------------------------------------------------------------------------
extern "C" void kernel_launch(void* const* d_in, const int* in_sizes, int n_in,
                              void* d_out, int out_size)
{
    const float* h_bsd = (const float*)d_in[0];
    const float* w_q   = (const float*)d_in[1];
    const float* w_k   = (const float*)d_in[2];
    const float* w_v   = (const float*)d_in[3];
    const float* w_o   = (const float*)d_in[4];
    float* out = (float*)d_out;

    float* Qb; cudaGetSymbolAddress((void**)&Qb, g_Q);
    float* Kb; cudaGetSymbolAddress((void**)&Kb, g_K);
    float* Vb; cudaGetSymbolAddress((void**)&Vb, g_V);
    float* Ab; cudaGetSymbolAddress((void**)&Ab, g_A);

    const int M = B_ * S_;           // 4096

    dim3 gq(DMODEL / BN, M / BM);    // (32, 64)
    dim3 gkv(KVDIM / BN, M / BM);    // (8, 64)

    sgemm_abt<<<gq, 256>>>(h_bsd, w_q, Qb, M, DMODEL, DMODEL);
    sgemm_abt<<<gkv, 256>>>(h_bsd, w_k, Kb, M, KVDIM, DMODEL);
    sgemm_abt<<<gkv, 256>>>(h_bsd, w_v, Vb, M, KVDIM, DMODEL);

    flash_attn<<<dim3(S_ / 128, NQH, B_), 128>>>(Qb, Kb, Vb, Ab);

    sgemm_abt<<<gq, 256>>>(Ab, w_o, out, M, DMODEL, DMODEL);
}

// round 4
// speedup vs baseline: 1.4461x; 1.4461x over previous
#include <cuda_runtime.h>
#include <cuda_bf16.h>
#include <math.h>
#include <stdint.h>

// Problem constants
#define B_      2
#define S_      2048
#define DMODEL  2048
#define NQH     32
#define NKVH    8
#define HD      64
#define KVDIM   (NKVH * HD)   // 512
#define MROWS   (B_ * S_)     // 4096
#define K3      (3 * DMODEL)  // 6144: [hi | hi | lo] x [hi | lo | hi]

// ---------------------------------------------------------------------------
// Scratch (__device__ globals; no allocation allowed)
// ---------------------------------------------------------------------------
__device__ float g_Q[MROWS * DMODEL];            // 32 MB
__device__ float g_K[MROWS * KVDIM];             //  8 MB
__device__ float g_V[MROWS * KVDIM];             //  8 MB
__device__ float g_A[MROWS * DMODEL];            // 32 MB attention out
__device__ __nv_bfloat16 g_X3 [MROWS * K3];      // 48 MB  activations (A-side)
__device__ __nv_bfloat16 g_Wq3[DMODEL * K3];     // 24 MB  (B-side)
__device__ __nv_bfloat16 g_Wk3[KVDIM * K3];      //  6 MB
__device__ __nv_bfloat16 g_Wv3[KVDIM * K3];      //  6 MB
__device__ __nv_bfloat16 g_Wo3[DMODEL * K3];     // 24 MB
__device__ __nv_bfloat16 g_A3 [MROWS * K3];      // 48 MB

// ---------------------------------------------------------------------------
// 3-way split fp32 -> bf16 along K.  Row stride 3K.
// mode 0 (A-side): [hi | hi | lo]      mode 1 (B-side): [hi | lo | hi]
// Dot over 3K = Ah.Bh + Ah.Bl + Al.Bh  (drops only Al.Bl ~ 2^-18)
// ---------------------------------------------------------------------------
__global__ void split3_bf16(const float* __restrict__ X,
                            __nv_bfloat16* __restrict__ Y, int R, int K, int mode)
{
    const int total = R * K / 4;
    for (int i = blockIdx.x * blockDim.x + threadIdx.x; i < total;
         i += gridDim.x * blockDim.x) {
        const int idx = i * 4;
        const int r = idx / K;
        const int k = idx % K;
        float4 x = *(const float4*)(X + idx);
        __nv_bfloat16 h0 = __float2bfloat16(x.x);
        __nv_bfloat16 h1 = __float2bfloat16(x.y);
        __nv_bfloat16 h2 = __float2bfloat16(x.z);
        __nv_bfloat16 h3 = __float2bfloat16(x.w);
        __nv_bfloat162 hi0; hi0.x = h0; hi0.y = h1;
        __nv_bfloat162 hi1; hi1.x = h2; hi1.y = h3;
        __nv_bfloat162 lo0;
        lo0.x = __float2bfloat16(x.x - __bfloat162float(h0));
        lo0.y = __float2bfloat16(x.y - __bfloat162float(h1));
        __nv_bfloat162 lo1;
        lo1.x = __float2bfloat16(x.z - __bfloat162float(h2));
        lo1.y = __float2bfloat16(x.w - __bfloat162float(h3));

        __nv_bfloat16* row = Y + (size_t)r * 3 * K;
        const int off_hi2 = mode ? 2 * K : K;     // second hi copy
        const int off_lo  = mode ? K     : 2 * K; // lo slot
        __nv_bfloat162* y0 = (__nv_bfloat162*)(row + k);
        __nv_bfloat162* y1 = (__nv_bfloat162*)(row + off_hi2 + k);
        __nv_bfloat162* y2 = (__nv_bfloat162*)(row + off_lo + k);
        y0[0] = hi0; y0[1] = hi1;
        y1[0] = hi0; y1[1] = hi1;
        y2[0] = lo0; y2[1] = lo1;
    }
}

// ---------------------------------------------------------------------------
// bf16 tensor-core GEMM: C[M,N] (fp32) = A[M,Kk] * B[N,Kk]^T
// CTA 128x128, BK=32, 256 threads = 8 warps (2 x 4), warp tile 64x32.
// cp.async double-buffered smem, ldmatrix + mma.sync.m16n8k16.
// ---------------------------------------------------------------------------
#define GBM 128
#define GBN 128
#define GBK 32
#define PAD 8
#define LDSR (GBK + PAD)   // 40 bf16 per smem row

__device__ __forceinline__ uint32_t smem_u32(const void* p) {
    return (uint32_t)__cvta_generic_to_shared(p);
}

__global__ void __launch_bounds__(256) gemm_bf16_tc(
    const __nv_bfloat16* __restrict__ A,
    const __nv_bfloat16* __restrict__ Bm,
    float* __restrict__ C, int M, int N, int Kk)
{
    __shared__ __nv_bfloat16 sA[2][GBM * LDSR];
    __shared__ __nv_bfloat16 sB[2][GBN * LDSR];

    const int tid  = threadIdx.x;
    const int lane = tid & 31;
    const int wid  = tid >> 5;
    const int wm   = wid >> 2;        // 0..1  -> 64-row slab
    const int wn   = wid & 3;         // 0..3  -> 32-col slab
    const int bm   = blockIdx.y * GBM;
    const int bn   = blockIdx.x * GBN;

    const int lrow = tid >> 1;
    const int lcol = (tid & 1) * 16;

    float acc[4][4][4];
    #pragma unroll
    for (int mi = 0; mi < 4; mi++)
        #pragma unroll
        for (int ni = 0; ni < 4; ni++)
            #pragma unroll
            for (int r = 0; r < 4; r++) acc[mi][ni][r] = 0.0f;

    const int NT = Kk / GBK;

    auto load_stage = [&](int buf, int k0) {
        const __nv_bfloat16* ga = A  + (size_t)(bm + lrow) * Kk + k0 + lcol;
        const __nv_bfloat16* gb = Bm + (size_t)(bn + lrow) * Kk + k0 + lcol;
        uint32_t sa = smem_u32(&sA[buf][lrow * LDSR + lcol]);
        uint32_t sb = smem_u32(&sB[buf][lrow * LDSR + lcol]);
        asm volatile("cp.async.cg.shared.global [%0], [%1], 16;\n" :: "r"(sa), "l"(ga));
        asm volatile("cp.async.cg.shared.global [%0], [%1], 16;\n" :: "r"(sa + 16), "l"(ga + 8));
        asm volatile("cp.async.cg.shared.global [%0], [%1], 16;\n" :: "r"(sb), "l"(gb));
        asm volatile("cp.async.cg.shared.global [%0], [%1], 16;\n" :: "r"(sb + 16), "l"(gb + 8));
    };

    load_stage(0, 0);
    asm volatile("cp.async.commit_group;\n");

    for (int kt = 0; kt < NT; kt++) {
        const int cur = kt & 1;
        if (kt + 1 < NT) load_stage(1 - cur, (kt + 1) * GBK);
        asm volatile("cp.async.commit_group;\n");
        asm volatile("cp.async.wait_group 1;\n");
        __syncthreads();

        #pragma unroll
        for (int kk = 0; kk < GBK; kk += 16) {
            uint32_t af[4][4];
            uint32_t bf[4][2];
            #pragma unroll
            for (int mi = 0; mi < 4; mi++) {
                const int row = wm * 64 + mi * 16 + (lane & 15);
                const int col = kk + ((lane >> 4) << 3);
                uint32_t addr = smem_u32(&sA[cur][row * LDSR + col]);
                asm volatile("ldmatrix.sync.aligned.m8n8.x4.shared.b16 {%0,%1,%2,%3}, [%4];"
                             : "=r"(af[mi][0]), "=r"(af[mi][1]), "=r"(af[mi][2]), "=r"(af[mi][3])
                             : "r"(addr));
            }
            #pragma unroll
            for (int ni = 0; ni < 4; ni++) {
                const int row = wn * 32 + ni * 8 + (lane & 7);
                const int col = kk + (((lane >> 3) & 1) << 3);
                uint32_t addr = smem_u32(&sB[cur][row * LDSR + col]);
                asm volatile("ldmatrix.sync.aligned.m8n8.x2.shared.b16 {%0,%1}, [%2];"
                             : "=r"(bf[ni][0]), "=r"(bf[ni][1]) : "r"(addr));
            }
            #pragma unroll
            for (int mi = 0; mi < 4; mi++)
                #pragma unroll
                for (int ni = 0; ni < 4; ni++) {
                    asm volatile(
                        "mma.sync.aligned.m16n8k16.row.col.f32.bf16.bf16.f32 "
                        "{%0,%1,%2,%3}, {%4,%5,%6,%7}, {%8,%9}, {%0,%1,%2,%3};"
                        : "+f"(acc[mi][ni][0]), "+f"(acc[mi][ni][1]),
                          "+f"(acc[mi][ni][2]), "+f"(acc[mi][ni][3])
                        : "r"(af[mi][0]), "r"(af[mi][1]), "r"(af[mi][2]), "r"(af[mi][3]),
                          "r"(bf[ni][0]), "r"(bf[ni][1]));
                }
        }
        __syncthreads();
    }

    #pragma unroll
    for (int mi = 0; mi < 4; mi++) {
        const int r0 = bm + wm * 64 + mi * 16 + (lane >> 2);
        #pragma unroll
        for (int ni = 0; ni < 4; ni++) {
            const int c0 = bn + wn * 32 + ni * 8 + 2 * (lane & 3);
            float2 v0 = make_float2(acc[mi][ni][0], acc[mi][ni][1]);
            float2 v1 = make_float2(acc[mi][ni][2], acc[mi][ni][3]);
            *(float2*)(C + (size_t)r0 * N + c0)       = v0;
            *(float2*)(C + (size_t)(r0 + 8) * N + c0) = v1;
        }
    }
}

// ---------------------------------------------------------------------------
// Flash-style attention (fp32, online softmax).
// 4-way ILP on the q.k dot product (was latency-bound on 1 accumulator).
// ---------------------------------------------------------------------------
__global__ void __launch_bounds__(128) flash_attn(
    const float* __restrict__ Q, const float* __restrict__ K,
    const float* __restrict__ V, float* __restrict__ O)
{
    __shared__ float Ks[64][HD];
    __shared__ float Vs[64][HD];

    const int b = blockIdx.z;
    const int h = blockIdx.y;
    const int row = blockIdx.x * 128 + threadIdx.x;
    const int kvh = h / (NQH / NKVH);

    const float* qptr = Q + ((size_t)(b * S_ + row) * DMODEL) + h * HD;
    const float* kbase = K + (size_t)b * S_ * KVDIM + kvh * HD;
    const float* vbase = V + (size_t)b * S_ * KVDIM + kvh * HD;

    float q[HD];
    #pragma unroll
    for (int d = 0; d < HD; d++) q[d] = qptr[d] * 0.125f;

    float out[HD];
    #pragma unroll
    for (int d = 0; d < HD; d++) out[d] = 0.0f;
    float m = -1e30f, l = 0.0f;

    for (int t = 0; t < S_; t += 64) {
        for (int i = threadIdx.x; i < 64 * 16; i += 128) {
            const int r = i / 16;
            const int c = (i % 16) * 4;
            *(float4*)&Ks[r][c] = *(const float4*)(kbase + (size_t)(t + r) * KVDIM + c);
            *(float4*)&Vs[r][c] = *(const float4*)(vbase + (size_t)(t + r) * KVDIM + c);
        }
        __syncthreads();

        for (int j = 0; j < 64; j++) {
            float s0 = 0.0f, s1 = 0.0f, s2 = 0.0f, s3 = 0.0f;
            #pragma unroll
            for (int d = 0; d < HD; d += 4) {
                s0 = fmaf(q[d + 0], Ks[j][d + 0], s0);
                s1 = fmaf(q[d + 1], Ks[j][d + 1], s1);
                s2 = fmaf(q[d + 2], Ks[j][d + 2], s2);
                s3 = fmaf(q[d + 3], Ks[j][d + 3], s3);
            }
            const float s = (s0 + s1) + (s2 + s3);
            if (s > m) {
                const float c = __expf(m - s);
                l *= c;
                #pragma unroll
                for (int d = 0; d < HD; d++) out[d] *= c;
                m = s;
            }
            const float p = __expf(s - m);
            l += p;
            #pragma unroll
            for (int d = 0; d < HD; d++) out[d] = fmaf(p, Vs[j][d], out[d]);
        }
        __syncthreads();
    }

    const float inv = 1.0f / l;
    float* optr = O + ((size_t)(b * S_ + row) * DMODEL) + h * HD;
    #pragma unroll
    for (int d = 0; d < HD; d++) optr[d] = out[d] * inv;
}

// ---------------------------------------------------------------------------
// Launch
// ---------------------------------------------------------------------------
extern "C" void kernel_launch(void* const* d_in, const int* in_sizes, int n_in,
                              void* d_out, int out_size)
{
    const float* h_bsd = (const float*)d_in[0];
    const float* w_q   = (const float*)d_in[1];
    const float* w_k   = (const float*)d_in[2];
    const float* w_v   = (const float*)d_in[3];
    const float* w_o   = (const float*)d_in[4];
    float* out = (float*)d_out;

    float *Qb, *Kb, *Vb, *Ab;
    __nv_bfloat16 *X3, *Wq3, *Wk3, *Wv3, *Wo3, *A3;
    cudaGetSymbolAddress((void**)&Qb, g_Q);
    cudaGetSymbolAddress((void**)&Kb, g_K);
    cudaGetSymbolAddress((void**)&Vb, g_V);
    cudaGetSymbolAddress((void**)&Ab, g_A);
    cudaGetSymbolAddress((void**)&X3, g_X3);
    cudaGetSymbolAddress((void**)&Wq3, g_Wq3);
    cudaGetSymbolAddress((void**)&Wk3, g_Wk3);
    cudaGetSymbolAddress((void**)&Wv3, g_Wv3);
    cudaGetSymbolAddress((void**)&Wo3, g_Wo3);
    cudaGetSymbolAddress((void**)&A3, g_A3);

    const int CV = 256;
    // A-side operands: mode 0 ([hi|hi|lo]); B-side: mode 1 ([hi|lo|hi])
    split3_bf16<<<512, CV>>>(h_bsd, X3, MROWS, DMODEL, 0);
    split3_bf16<<<512, CV>>>(w_q, Wq3, DMODEL, DMODEL, 1);
    split3_bf16<<<256, CV>>>(w_k, Wk3, KVDIM, DMODEL, 1);
    split3_bf16<<<256, CV>>>(w_v, Wv3, KVDIM, DMODEL, 1);
    split3_bf16<<<512, CV>>>(w_o, Wo3, DMODEL, DMODEL, 1);

    gemm_bf16_tc<<<dim3(DMODEL / GBN, MROWS / GBM), 256>>>(X3, Wq3, Qb, MROWS, DMODEL, K3);
    gemm_bf16_tc<<<dim3(KVDIM  / GBN, MROWS / GBM), 256>>>(X3, Wk3, Kb, MROWS, KVDIM, K3);
    gemm_bf16_tc<<<dim3(KVDIM  / GBN, MROWS / GBM), 256>>>(X3, Wv3, Vb, MROWS, KVDIM, K3);

    flash_attn<<<dim3(S_ / 128, NQH, B_), 128>>>(Qb, Kb, Vb, Ab);

    split3_bf16<<<512, CV>>>(Ab, A3, MROWS, DMODEL, 0);
    gemm_bf16_tc<<<dim3(DMODEL / GBN, MROWS / GBM), 256>>>(A3, Wo3, out, MROWS, DMODEL, K3);
}

// round 7
// speedup vs baseline: 2.7037x; 1.8697x over previous
#include <cuda_runtime.h>
#include <cuda_bf16.h>
#include <math.h>
#include <stdint.h>

// Problem constants
#define B_      2
#define S_      2048
#define DMODEL  2048
#define NQH     32
#define NKVH    8
#define HD      64
#define KVDIM   (NKVH * HD)   // 512
#define MROWS   (B_ * S_)     // 4096
#define K3      (3 * DMODEL)  // 6144: [hi | hi | lo] x [hi | lo | hi]

// ---------------------------------------------------------------------------
// Scratch (__device__ globals; no allocation allowed)
// ---------------------------------------------------------------------------
__device__ float g_A[MROWS * DMODEL];            // attention out fp32
__device__ __nv_bfloat16 g_X3 [MROWS * K3];
__device__ __nv_bfloat16 g_Wq3[DMODEL * K3];
__device__ __nv_bfloat16 g_Wk3[KVDIM * K3];
__device__ __nv_bfloat16 g_Wv3[KVDIM * K3];
__device__ __nv_bfloat16 g_Wo3[DMODEL * K3];
__device__ __nv_bfloat16 g_A3 [MROWS * K3];
__device__ __nv_bfloat16 g_Qh[MROWS * DMODEL], g_Ql[MROWS * DMODEL];
__device__ __nv_bfloat16 g_Kh[MROWS * KVDIM],  g_Kl[MROWS * KVDIM];
__device__ __nv_bfloat16 g_Vh[MROWS * KVDIM],  g_Vl[MROWS * KVDIM];

// ---------------------------------------------------------------------------
// helpers
// ---------------------------------------------------------------------------
__device__ __forceinline__ uint32_t smem_u32(const void* p) {
    return (uint32_t)__cvta_generic_to_shared(p);
}

// pack (a,b) -> bf16x2 hi, and their residuals -> bf16x2 lo
__device__ __forceinline__ uint32_t packsplit(float a, float b, uint32_t& lo) {
    __nv_bfloat16 ha = __float2bfloat16(a), hb = __float2bfloat16(b);
    __nv_bfloat16 la = __float2bfloat16(a - __bfloat162float(ha));
    __nv_bfloat16 lb = __float2bfloat16(b - __bfloat162float(hb));
    lo = ((uint32_t)__bfloat16_as_ushort(lb) << 16) | (uint32_t)__bfloat16_as_ushort(la);
    return ((uint32_t)__bfloat16_as_ushort(hb) << 16) | (uint32_t)__bfloat16_as_ushort(ha);
}

__device__ __forceinline__ void mma16816(float* c, const uint32_t* a, const uint32_t* b) {
    asm volatile(
        "mma.sync.aligned.m16n8k16.row.col.f32.bf16.bf16.f32 "
        "{%0,%1,%2,%3}, {%4,%5,%6,%7}, {%8,%9}, {%0,%1,%2,%3};"
        : "+f"(c[0]), "+f"(c[1]), "+f"(c[2]), "+f"(c[3])
        : "r"(a[0]), "r"(a[1]), "r"(a[2]), "r"(a[3]), "r"(b[0]), "r"(b[1]));
}

__device__ __forceinline__ void ldsm_x2(uint32_t& r0, uint32_t& r1, uint32_t addr) {
    asm volatile("ldmatrix.sync.aligned.m8n8.x2.shared.b16 {%0,%1}, [%2];"
                 : "=r"(r0), "=r"(r1) : "r"(addr));
}
__device__ __forceinline__ void ldsm_x2_t(uint32_t& r0, uint32_t& r1, uint32_t addr) {
    asm volatile("ldmatrix.sync.aligned.m8n8.x2.trans.shared.b16 {%0,%1}, [%2];"
                 : "=r"(r0), "=r"(r1) : "r"(addr));
}

// SW128 swizzle on a byte offset whose row stride is 128B
#define SW(a) ((a) ^ (((a) >> 3) & 0x70))

// ---------------------------------------------------------------------------
// 3-way split fp32 -> bf16 along K (for the projection GEMM operands).
// mode 0 (A-side): [hi | hi | lo]      mode 1 (B-side): [hi | lo | hi]
// ---------------------------------------------------------------------------
__global__ void split3_bf16(const float* __restrict__ X,
                            __nv_bfloat16* __restrict__ Y, int R, int K, int mode)
{
    const int total = R * K / 4;
    for (int i = blockIdx.x * blockDim.x + threadIdx.x; i < total;
         i += gridDim.x * blockDim.x) {
        const int idx = i * 4;
        const int r = idx / K;
        const int k = idx % K;
        float4 x = *(const float4*)(X + idx);
        uint32_t lo0, lo1;
        uint32_t hi0 = packsplit(x.x, x.y, lo0);
        uint32_t hi1 = packsplit(x.z, x.w, lo1);
        __nv_bfloat16* row = Y + (size_t)r * 3 * K;
        const int off_hi2 = mode ? 2 * K : K;
        const int off_lo  = mode ? K     : 2 * K;
        uint32_t* y0 = (uint32_t*)(row + k);
        uint32_t* y1 = (uint32_t*)(row + off_hi2 + k);
        uint32_t* y2 = (uint32_t*)(row + off_lo + k);
        y0[0] = hi0; y0[1] = hi1;
        y1[0] = hi0; y1[1] = hi1;
        y2[0] = lo0; y2[1] = lo1;
    }
}

// ---------------------------------------------------------------------------
// bf16 tensor-core GEMM: C = A[M,Kk] * B[N,Kk]^T
// If Chi != nullptr: write bf16 hi/lo split output (scaled); else fp32 C.
// ---------------------------------------------------------------------------
#define GBM 128
#define GBN 128
#define GBK 32
#define PAD 8
#define LDSR (GBK + PAD)

__global__ void __launch_bounds__(256) gemm_bf16_tc(
    const __nv_bfloat16* __restrict__ A,
    const __nv_bfloat16* __restrict__ Bm,
    float* __restrict__ C,
    __nv_bfloat16* __restrict__ Chi, __nv_bfloat16* __restrict__ Clo,
    float cscale, int M, int N, int Kk)
{
    __shared__ __nv_bfloat16 sA[2][GBM * LDSR];
    __shared__ __nv_bfloat16 sB[2][GBN * LDSR];

    const int tid  = threadIdx.x;
    const int lane = tid & 31;
    const int wid  = tid >> 5;
    const int wm   = wid >> 2;
    const int wn   = wid & 3;
    const int bm   = blockIdx.y * GBM;
    const int bn   = blockIdx.x * GBN;

    const int lrow = tid >> 1;
    const int lcol = (tid & 1) * 16;

    float acc[4][4][4];
    #pragma unroll
    for (int mi = 0; mi < 4; mi++)
        #pragma unroll
        for (int ni = 0; ni < 4; ni++)
            #pragma unroll
            for (int r = 0; r < 4; r++) acc[mi][ni][r] = 0.0f;

    const int NT = Kk / GBK;

    auto load_stage = [&](int buf, int k0) {
        const __nv_bfloat16* ga = A  + (size_t)(bm + lrow) * Kk + k0 + lcol;
        const __nv_bfloat16* gb = Bm + (size_t)(bn + lrow) * Kk + k0 + lcol;
        uint32_t sa = smem_u32(&sA[buf][lrow * LDSR + lcol]);
        uint32_t sb = smem_u32(&sB[buf][lrow * LDSR + lcol]);
        asm volatile("cp.async.cg.shared.global [%0], [%1], 16;\n" :: "r"(sa), "l"(ga));
        asm volatile("cp.async.cg.shared.global [%0], [%1], 16;\n" :: "r"(sa + 16), "l"(ga + 8));
        asm volatile("cp.async.cg.shared.global [%0], [%1], 16;\n" :: "r"(sb), "l"(gb));
        asm volatile("cp.async.cg.shared.global [%0], [%1], 16;\n" :: "r"(sb + 16), "l"(gb + 8));
    };

    load_stage(0, 0);
    asm volatile("cp.async.commit_group;\n");

    for (int kt = 0; kt < NT; kt++) {
        const int cur = kt & 1;
        if (kt + 1 < NT) load_stage(1 - cur, (kt + 1) * GBK);
        asm volatile("cp.async.commit_group;\n");
        asm volatile("cp.async.wait_group 1;\n");
        __syncthreads();

        #pragma unroll
        for (int kk = 0; kk < GBK; kk += 16) {
            uint32_t af[4][4];
            uint32_t bf[4][2];
            #pragma unroll
            for (int mi = 0; mi < 4; mi++) {
                const int row = wm * 64 + mi * 16 + (lane & 15);
                const int col = kk + ((lane >> 4) << 3);
                uint32_t addr = smem_u32(&sA[cur][row * LDSR + col]);
                asm volatile("ldmatrix.sync.aligned.m8n8.x4.shared.b16 {%0,%1,%2,%3}, [%4];"
                             : "=r"(af[mi][0]), "=r"(af[mi][1]), "=r"(af[mi][2]), "=r"(af[mi][3])
                             : "r"(addr));
            }
            #pragma unroll
            for (int ni = 0; ni < 4; ni++) {
                const int row = wn * 32 + ni * 8 + (lane & 7);
                const int col = kk + (((lane >> 3) & 1) << 3);
                uint32_t addr = smem_u32(&sB[cur][row * LDSR + col]);
                ldsm_x2(bf[ni][0], bf[ni][1], addr);
            }
            #pragma unroll
            for (int mi = 0; mi < 4; mi++)
                #pragma unroll
                for (int ni = 0; ni < 4; ni++)
                    mma16816(acc[mi][ni], af[mi], bf[ni]);
        }
        __syncthreads();
    }

    if (Chi) {
        #pragma unroll
        for (int mi = 0; mi < 4; mi++) {
            const int r0 = bm + wm * 64 + mi * 16 + (lane >> 2);
            #pragma unroll
            for (int ni = 0; ni < 4; ni++) {
                const int c0 = bn + wn * 32 + ni * 8 + 2 * (lane & 3);
                uint32_t lo0, lo1;
                uint32_t hi0 = packsplit(acc[mi][ni][0] * cscale, acc[mi][ni][1] * cscale, lo0);
                uint32_t hi1 = packsplit(acc[mi][ni][2] * cscale, acc[mi][ni][3] * cscale, lo1);
                *(uint32_t*)(Chi + (size_t)r0 * N + c0)       = hi0;
                *(uint32_t*)(Clo + (size_t)r0 * N + c0)       = lo0;
                *(uint32_t*)(Chi + (size_t)(r0 + 8) * N + c0) = hi1;
                *(uint32_t*)(Clo + (size_t)(r0 + 8) * N + c0) = lo1;
            }
        }
    } else {
        #pragma unroll
        for (int mi = 0; mi < 4; mi++) {
            const int r0 = bm + wm * 64 + mi * 16 + (lane >> 2);
            #pragma unroll
            for (int ni = 0; ni < 4; ni++) {
                const int c0 = bn + wn * 32 + ni * 8 + 2 * (lane & 3);
                *(float2*)(C + (size_t)r0 * N + c0)       = make_float2(acc[mi][ni][0], acc[mi][ni][1]);
                *(float2*)(C + (size_t)(r0 + 8) * N + c0) = make_float2(acc[mi][ni][2], acc[mi][ni][3]);
            }
        }
    }
}

// ---------------------------------------------------------------------------
// Tensor-core flash attention with hi/lo split precision.
// Block = 128 q-rows of one (b, h); 8 warps x m16. K/V l-tiles of 64,
// double-buffered swizzled smem. S = QhKh + QhKl + QlKh ; O += PhVh+PhVl+PlVh.
// ---------------------------------------------------------------------------
#define ATT_TILE_BYTES 8192                 // one 64x64 bf16 tile (swizzled, stride 128B)
#define ATT_BUF_BYTES  (4 * ATT_TILE_BYTES) // Kh,Kl,Vh,Vl
#define ATT_SMEM       (2 * ATT_BUF_BYTES)  // double buffer = 64 KB

__global__ void __launch_bounds__(256) flash_attn_mma(
    const __nv_bfloat16* __restrict__ Qh, const __nv_bfloat16* __restrict__ Ql,
    const __nv_bfloat16* __restrict__ Kh, const __nv_bfloat16* __restrict__ Kl,
    const __nv_bfloat16* __restrict__ Vh, const __nv_bfloat16* __restrict__ Vl,
    float* __restrict__ O)
{
    extern __shared__ __nv_bfloat16 smem[];
    const uint32_t sbase = smem_u32(smem);

    const int b    = blockIdx.z;
    const int h    = blockIdx.y;
    const int kvh  = h >> 2;
    const int tid  = threadIdx.x;
    const int lane = tid & 31;
    const int w    = tid >> 5;
    const int qrow = blockIdx.x * 128 + w * 16;

    // ---- load Q fragments (resident): qf[hi/lo][kt][reg]
    uint32_t qf[2][4][4];
    {
        const size_t base = ((size_t)(b * S_ + qrow + (lane >> 2))) * DMODEL + h * HD + (lane & 3) * 2;
        #pragma unroll
        for (int kt = 0; kt < 4; kt++) {
            const size_t c = base + kt * 16;
            qf[0][kt][0] = *(const uint32_t*)(Qh + c);
            qf[0][kt][1] = *(const uint32_t*)(Qh + c + 8 * DMODEL);
            qf[0][kt][2] = *(const uint32_t*)(Qh + c + 8);
            qf[0][kt][3] = *(const uint32_t*)(Qh + c + 8 * DMODEL + 8);
            qf[1][kt][0] = *(const uint32_t*)(Ql + c);
            qf[1][kt][1] = *(const uint32_t*)(Ql + c + 8 * DMODEL);
            qf[1][kt][2] = *(const uint32_t*)(Ql + c + 8);
            qf[1][kt][3] = *(const uint32_t*)(Ql + c + 8 * DMODEL + 8);
        }
    }

    float o[8][4];
    #pragma unroll
    for (int nt = 0; nt < 8; nt++)
        #pragma unroll
        for (int r = 0; r < 4; r++) o[nt][r] = 0.0f;
    float m0 = -1e30f, m1 = -1e30f, l0 = 0.0f, l1 = 0.0f;

    // tile loader: 4 tiles (Kh,Kl,Vh,Vl), each 64 rows x 128B, swizzled
    const __nv_bfloat16* gsrc[4] = {
        Kh + (size_t)b * S_ * KVDIM + kvh * HD,
        Kl + (size_t)b * S_ * KVDIM + kvh * HD,
        Vh + (size_t)b * S_ * KVDIM + kvh * HD,
        Vl + (size_t)b * S_ * KVDIM + kvh * HD };
    const int lrow = tid >> 2;         // 0..63
    const int lc   = tid & 3;          // 16B chunk 0..3 (and +4)

    auto load_tiles = [&](int buf, int lt) {
        #pragma unroll
        for (int t = 0; t < 4; t++) {
            const __nv_bfloat16* src = gsrc[t] + (size_t)(lt * 64 + lrow) * KVDIM;
            uint32_t dbase = sbase + buf * ATT_BUF_BYTES + t * ATT_TILE_BYTES;
            uint32_t d0 = dbase + SW(lrow * 128 + lc * 16);
            uint32_t d1 = dbase + SW(lrow * 128 + (lc + 4) * 16);
            asm volatile("cp.async.cg.shared.global [%0], [%1], 16;\n" :: "r"(d0), "l"(src + lc * 8));
            asm volatile("cp.async.cg.shared.global [%0], [%1], 16;\n" :: "r"(d1), "l"(src + (lc + 4) * 8));
        }
    };

    load_tiles(0, 0);
    asm volatile("cp.async.commit_group;\n");

    const int l7  = lane & 7;
    const int l15 = lane & 15;
    const int khalf = ((lane >> 3) & 1) * 16;   // +16B for second 8x8 of x2 (non-trans)

    for (int lt = 0; lt < S_ / 64; lt++) {
        const int cur = lt & 1;
        if (lt + 1 < S_ / 64) load_tiles(1 - cur, lt + 1);
        asm volatile("cp.async.commit_group;\n");
        asm volatile("cp.async.wait_group 1;\n");
        __syncthreads();

        const uint32_t tb = sbase + cur * ATT_BUF_BYTES;

        // ---- S = Q K^T (3-term split)
        float s[8][4];
        #pragma unroll
        for (int nt = 0; nt < 8; nt++)
            #pragma unroll
            for (int r = 0; r < 4; r++) s[nt][r] = 0.0f;

        #pragma unroll
        for (int nt = 0; nt < 8; nt++) {
            #pragma unroll
            for (int kt = 0; kt < 4; kt++) {
                const uint32_t inner = (uint32_t)((nt * 8 + l7) * 128 + kt * 32 + khalf);
                uint32_t bh[2], bl[2];
                ldsm_x2(bh[0], bh[1], tb + 0 * ATT_TILE_BYTES + SW(inner));
                ldsm_x2(bl[0], bl[1], tb + 1 * ATT_TILE_BYTES + SW(inner));
                mma16816(s[nt], qf[0][kt], bh);
                mma16816(s[nt], qf[0][kt], bl);
                mma16816(s[nt], qf[1][kt], bh);
            }
        }

        // ---- online softmax
        float mx0 = -1e30f, mx1 = -1e30f;
        #pragma unroll
        for (int nt = 0; nt < 8; nt++) {
            mx0 = fmaxf(mx0, fmaxf(s[nt][0], s[nt][1]));
            mx1 = fmaxf(mx1, fmaxf(s[nt][2], s[nt][3]));
        }
        mx0 = fmaxf(mx0, __shfl_xor_sync(0xffffffffu, mx0, 1));
        mx0 = fmaxf(mx0, __shfl_xor_sync(0xffffffffu, mx0, 2));
        mx1 = fmaxf(mx1, __shfl_xor_sync(0xffffffffu, mx1, 1));
        mx1 = fmaxf(mx1, __shfl_xor_sync(0xffffffffu, mx1, 2));
        const float mn0 = fmaxf(m0, mx0), mn1 = fmaxf(m1, mx1);
        const float sc0 = __expf(m0 - mn0), sc1 = __expf(m1 - mn1);
        m0 = mn0; m1 = mn1;
        l0 *= sc0; l1 *= sc1;
        #pragma unroll
        for (int nt = 0; nt < 8; nt++) {
            o[nt][0] *= sc0; o[nt][1] *= sc0; o[nt][2] *= sc1; o[nt][3] *= sc1;
        }
        #pragma unroll
        for (int nt = 0; nt < 8; nt++) {
            float p0 = __expf(s[nt][0] - m0), p1 = __expf(s[nt][1] - m0);
            float p2 = __expf(s[nt][2] - m1), p3 = __expf(s[nt][3] - m1);
            l0 += p0 + p1; l1 += p2 + p3;
            s[nt][0] = p0; s[nt][1] = p1; s[nt][2] = p2; s[nt][3] = p3;
        }

        // ---- P fragments (hi + lo)
        uint32_t ph[4][4], pl[4][4];
        #pragma unroll
        for (int lk = 0; lk < 4; lk++) {
            ph[lk][0] = packsplit(s[2*lk][0],   s[2*lk][1],   pl[lk][0]);
            ph[lk][1] = packsplit(s[2*lk][2],   s[2*lk][3],   pl[lk][1]);
            ph[lk][2] = packsplit(s[2*lk+1][0], s[2*lk+1][1], pl[lk][2]);
            ph[lk][3] = packsplit(s[2*lk+1][2], s[2*lk+1][3], pl[lk][3]);
        }

        // ---- O += P V (3-term split)
        #pragma unroll
        for (int nt = 0; nt < 8; nt++) {
            #pragma unroll
            for (int lk = 0; lk < 4; lk++) {
                const uint32_t inner = (uint32_t)((lk * 16 + l15) * 128 + nt * 16);
                uint32_t vh[2], vl[2];
                ldsm_x2_t(vh[0], vh[1], tb + 2 * ATT_TILE_BYTES + SW(inner));
                ldsm_x2_t(vl[0], vl[1], tb + 3 * ATT_TILE_BYTES + SW(inner));
                mma16816(o[nt], ph[lk], vh);
                mma16816(o[nt], ph[lk], vl);
                mma16816(o[nt], pl[lk], vh);
            }
        }
        __syncthreads();
    }

    // ---- epilogue
    l0 += __shfl_xor_sync(0xffffffffu, l0, 1);
    l0 += __shfl_xor_sync(0xffffffffu, l0, 2);
    l1 += __shfl_xor_sync(0xffffffffu, l1, 1);
    l1 += __shfl_xor_sync(0xffffffffu, l1, 2);
    const float inv0 = 1.0f / l0, inv1 = 1.0f / l1;

    float* po = O + ((size_t)(b * S_ + qrow + (lane >> 2))) * DMODEL + h * HD + (lane & 3) * 2;
    #pragma unroll
    for (int nt = 0; nt < 8; nt++) {
        *(float2*)(po + nt * 8)              = make_float2(o[nt][0] * inv0, o[nt][1] * inv0);
        *(float2*)(po + nt * 8 + 8 * DMODEL) = make_float2(o[nt][2] * inv1, o[nt][3] * inv1);
    }
}

// ---------------------------------------------------------------------------
// Launch
// ---------------------------------------------------------------------------
extern "C" void kernel_launch(void* const* d_in, const int* in_sizes, int n_in,
                              void* d_out, int out_size)
{
    const float* h_bsd = (const float*)d_in[0];
    const float* w_q   = (const float*)d_in[1];
    const float* w_k   = (const float*)d_in[2];
    const float* w_v   = (const float*)d_in[3];
    const float* w_o   = (const float*)d_in[4];
    float* out = (float*)d_out;

    float* Ab;
    __nv_bfloat16 *X3, *Wq3, *Wk3, *Wv3, *Wo3, *A3;
    __nv_bfloat16 *Qh, *Ql, *Kh, *Kl, *Vh, *Vl;
    cudaGetSymbolAddress((void**)&Ab, g_A);
    cudaGetSymbolAddress((void**)&X3, g_X3);
    cudaGetSymbolAddress((void**)&Wq3, g_Wq3);
    cudaGetSymbolAddress((void**)&Wk3, g_Wk3);
    cudaGetSymbolAddress((void**)&Wv3, g_Wv3);
    cudaGetSymbolAddress((void**)&Wo3, g_Wo3);
    cudaGetSymbolAddress((void**)&A3, g_A3);
    cudaGetSymbolAddress((void**)&Qh, g_Qh);
    cudaGetSymbolAddress((void**)&Ql, g_Ql);
    cudaGetSymbolAddress((void**)&Kh, g_Kh);
    cudaGetSymbolAddress((void**)&Kl, g_Kl);
    cudaGetSymbolAddress((void**)&Vh, g_Vh);
    cudaGetSymbolAddress((void**)&Vl, g_Vl);

    static int smem_set = 0;
    if (!smem_set) {
        cudaFuncSetAttribute(flash_attn_mma,
                             cudaFuncAttributeMaxDynamicSharedMemorySize, ATT_SMEM);
        smem_set = 1;
    }

    const int CV = 256;
    split3_bf16<<<512, CV>>>(h_bsd, X3, MROWS, DMODEL, 0);
    split3_bf16<<<512, CV>>>(w_q, Wq3, DMODEL, DMODEL, 1);
    split3_bf16<<<256, CV>>>(w_k, Wk3, KVDIM, DMODEL, 1);
    split3_bf16<<<256, CV>>>(w_v, Wv3, KVDIM, DMODEL, 1);
    split3_bf16<<<512, CV>>>(w_o, Wo3, DMODEL, DMODEL, 1);

    // Projections: emit hi/lo bf16 directly (Q pre-scaled by 1/sqrt(HD))
    gemm_bf16_tc<<<dim3(DMODEL / GBN, MROWS / GBM), 256>>>(
        X3, Wq3, nullptr, Qh, Ql, 0.125f, MROWS, DMODEL, K3);
    gemm_bf16_tc<<<dim3(KVDIM / GBN, MROWS / GBM), 256>>>(
        X3, Wk3, nullptr, Kh, Kl, 1.0f, MROWS, KVDIM, K3);
    gemm_bf16_tc<<<dim3(KVDIM / GBN, MROWS / GBM), 256>>>(
        X3, Wv3, nullptr, Vh, Vl, 1.0f, MROWS, KVDIM, K3);

    flash_attn_mma<<<dim3(S_ / 128, NQH, B_), 256, ATT_SMEM>>>(
        Qh, Ql, Kh, Kl, Vh, Vl, Ab);

    split3_bf16<<<512, CV>>>(Ab, A3, MROWS, DMODEL, 0);
    gemm_bf16_tc<<<dim3(DMODEL / GBN, MROWS / GBM), 256>>>(
        A3, Wo3, out, nullptr, nullptr, 1.0f, MROWS, DMODEL, K3);
}

// round 10
// speedup vs baseline: 2.9674x; 1.0975x over previous
#include <cuda_runtime.h>
#include <cuda_bf16.h>
#include <math.h>
#include <stdint.h>

// Problem constants
#define B_      2
#define S_      2048
#define DMODEL  2048
#define NQH     32
#define NKVH    8
#define HD      64
#define KVDIM   (NKVH * HD)   // 512
#define KVD2    (2 * KVDIM)   // 1024 (K and V fused)
#define MROWS   (B_ * S_)     // 4096

// ---------------------------------------------------------------------------
// Scratch (__device__ globals; no allocation allowed)
// ---------------------------------------------------------------------------
__device__ __nv_bfloat16 g_Xh [MROWS * DMODEL],  g_Xl [MROWS * DMODEL];
__device__ __nv_bfloat16 g_Wqh[DMODEL * DMODEL], g_Wql[DMODEL * DMODEL];
__device__ __nv_bfloat16 g_Wkvh[KVD2 * DMODEL],  g_Wkvl[KVD2 * DMODEL];
__device__ __nv_bfloat16 g_Woh[DMODEL * DMODEL], g_Wol[DMODEL * DMODEL];
__device__ __nv_bfloat16 g_Qh [MROWS * DMODEL],  g_Ql [MROWS * DMODEL];
__device__ __nv_bfloat16 g_KVh[MROWS * KVD2],    g_KVl[MROWS * KVD2];
__device__ __nv_bfloat16 g_AOh[MROWS * DMODEL],  g_AOl[MROWS * DMODEL];

// ---------------------------------------------------------------------------
// helpers
// ---------------------------------------------------------------------------
__device__ __forceinline__ uint32_t smem_u32(const void* p) {
    return (uint32_t)__cvta_generic_to_shared(p);
}

__device__ __forceinline__ uint32_t packsplit(float a, float b, uint32_t& lo) {
    __nv_bfloat16 ha = __float2bfloat16(a), hb = __float2bfloat16(b);
    __nv_bfloat16 la = __float2bfloat16(a - __bfloat162float(ha));
    __nv_bfloat16 lb = __float2bfloat16(b - __bfloat162float(hb));
    lo = ((uint32_t)__bfloat16_as_ushort(lb) << 16) | (uint32_t)__bfloat16_as_ushort(la);
    return ((uint32_t)__bfloat16_as_ushort(hb) << 16) | (uint32_t)__bfloat16_as_ushort(ha);
}

__device__ __forceinline__ float fexp2(float x) {
    float r;
    asm("ex2.approx.f32 %0, %1;" : "=f"(r) : "f"(x));
    return r;
}

__device__ __forceinline__ void mma16816(float* c, const uint32_t* a, const uint32_t* b) {
    asm volatile(
        "mma.sync.aligned.m16n8k16.row.col.f32.bf16.bf16.f32 "
        "{%0,%1,%2,%3}, {%4,%5,%6,%7}, {%8,%9}, {%0,%1,%2,%3};"
        : "+f"(c[0]), "+f"(c[1]), "+f"(c[2]), "+f"(c[3])
        : "r"(a[0]), "r"(a[1]), "r"(a[2]), "r"(a[3]), "r"(b[0]), "r"(b[1]));
}

__device__ __forceinline__ void ldsm_x4(uint32_t* r, uint32_t addr) {
    asm volatile("ldmatrix.sync.aligned.m8n8.x4.shared.b16 {%0,%1,%2,%3}, [%4];"
                 : "=r"(r[0]), "=r"(r[1]), "=r"(r[2]), "=r"(r[3]) : "r"(addr));
}
__device__ __forceinline__ void ldsm_x2(uint32_t& r0, uint32_t& r1, uint32_t addr) {
    asm volatile("ldmatrix.sync.aligned.m8n8.x2.shared.b16 {%0,%1}, [%2];"
                 : "=r"(r0), "=r"(r1) : "r"(addr));
}
__device__ __forceinline__ void ldsm_x2_t(uint32_t& r0, uint32_t& r1, uint32_t addr) {
    asm volatile("ldmatrix.sync.aligned.m8n8.x2.trans.shared.b16 {%0,%1}, [%2];"
                 : "=r"(r0), "=r"(r1) : "r"(addr));
}

#define SW(a) ((a) ^ (((a) >> 3) & 0x70))

__device__ __forceinline__ void cp16(uint32_t d, const void* s) {
    asm volatile("cp.async.cg.shared.global [%0], [%1], 16;\n" :: "r"(d), "l"(s));
}

// softmax scale: 1/sqrt(64) * log2(e)  (scores kept in log2 domain, ex2 softmax)
#define QSCALE 0.18033688011112042f

// ---------------------------------------------------------------------------
// fp32 -> (hi, lo) bf16 buffers (same layout as source).
// ---------------------------------------------------------------------------
__global__ void split2_bf16(const float* __restrict__ X,
                            __nv_bfloat16* __restrict__ Yh,
                            __nv_bfloat16* __restrict__ Yl, int total4)
{
    for (int i = blockIdx.x * blockDim.x + threadIdx.x; i < total4;
         i += gridDim.x * blockDim.x) {
        const int idx = i * 4;
        float4 x = *(const float4*)(X + idx);
        uint32_t lo0, lo1;
        uint32_t hi0 = packsplit(x.x, x.y, lo0);
        uint32_t hi1 = packsplit(x.z, x.w, lo1);
        *(uint2*)(Yh + idx) = make_uint2(hi0, hi1);
        *(uint2*)(Yl + idx) = make_uint2(lo0, lo1);
    }
}

// ---------------------------------------------------------------------------
// Split-precision GEMM on mma.sync:
//   C[M,N] = (Ah+Al)[M,K] * (Bh+Bl)[N,K]^T  via  AhBh + AhBl + AlBh
// CTA 128x256, 8 warps (2M x 4N) at 64x64 each, BK=32, 2-stage cp.async.
// Output: fp32 C, or hi/lo bf16 (Chi/Clo) scaled by cscale.
// ---------------------------------------------------------------------------
#define TCM 128
#define TCN 256
#define TCK 32
#define LDSR 40                         // 32 + 8 pad (elements)
#define SA_BYTES (TCM * LDSR * 2)       // 10240
#define SB_BYTES (TCN * LDSR * 2)       // 20480
#define STAGE_BYTES (2 * SA_BYTES + 2 * SB_BYTES)   // 61440
#define GEMM_SMEM (2 * STAGE_BYTES)                 // 122880

__global__ void __launch_bounds__(256, 1) gemm_split(
    const __nv_bfloat16* __restrict__ Ah, const __nv_bfloat16* __restrict__ Al,
    const __nv_bfloat16* __restrict__ Bh, const __nv_bfloat16* __restrict__ Bl,
    float* __restrict__ C,
    __nv_bfloat16* __restrict__ Chi, __nv_bfloat16* __restrict__ Clo,
    float cscale, int M, int N, int Kk)
{
    extern __shared__ __align__(128) char sm[];
    const uint32_t sb = smem_u32(sm);

    const int tid  = threadIdx.x;
    const int lane = tid & 31;
    const int w    = tid >> 5;
    const int wm   = (w & 1) * 64;      // M slab
    const int wn   = (w >> 1) * 64;     // N slab
    const int bm   = blockIdx.y * TCM;
    const int bn   = blockIdx.x * TCN;

    float acc[4][8][4];
    #pragma unroll
    for (int mi = 0; mi < 4; mi++)
        #pragma unroll
        for (int nt = 0; nt < 8; nt++)
            #pragma unroll
            for (int r = 0; r < 4; r++) acc[mi][nt][r] = 0.0f;

    // load mapping: A 128 rows x 2 chunkpairs; B 256 rows x 4 chunks
    const int arow = tid >> 1, acp = (tid & 1) * 16;
    const __nv_bfloat16* gAh = Ah + (size_t)(bm + arow) * Kk + acp;
    const __nv_bfloat16* gAl = Al + (size_t)(bm + arow) * Kk + acp;
    const __nv_bfloat16* gBh = Bh + (size_t)(bn + tid) * Kk;
    const __nv_bfloat16* gBl = Bl + (size_t)(bn + tid) * Kk;
    const uint32_t aso = (uint32_t)(arow * LDSR + acp) * 2;
    const uint32_t bso = (uint32_t)(tid * LDSR) * 2;

    auto load_stage = [&](int buf, int kt) {
        const uint32_t st = sb + buf * STAGE_BYTES;
        const int k0 = kt * TCK;
        #pragma unroll
        for (int j = 0; j < 2; j++) {
            cp16(st + aso + j * 16, gAh + k0 + j * 8);
            cp16(st + SA_BYTES + aso + j * 16, gAl + k0 + j * 8);
        }
        #pragma unroll
        for (int j = 0; j < 4; j++) {
            cp16(st + 2 * SA_BYTES + bso + j * 16, gBh + k0 + j * 8);
            cp16(st + 2 * SA_BYTES + SB_BYTES + bso + j * 16, gBl + k0 + j * 8);
        }
    };

    const int NT = Kk / TCK;
    load_stage(0, 0);
    asm volatile("cp.async.commit_group;\n");

    const int l15 = lane & 15;
    const int khalf = (lane >> 4) << 3;

    for (int kt = 0; kt < NT; kt++) {
        const int cur = kt & 1;
        if (kt + 1 < NT) {
            load_stage(1 - cur, kt + 1);
            asm volatile("cp.async.commit_group;\n");
            asm volatile("cp.async.wait_group 1;\n");
        } else {
            asm volatile("cp.async.wait_group 0;\n");
        }
        __syncthreads();

        const uint32_t sAh = sb + cur * STAGE_BYTES;
        const uint32_t sAl = sAh + SA_BYTES;
        const uint32_t sBh = sAh + 2 * SA_BYTES;
        const uint32_t sBl = sBh + SB_BYTES;

        #pragma unroll
        for (int kk = 0; kk < TCK; kk += 16) {
            uint32_t ah[4][4], al[4][4], bfr[8][2];
            #pragma unroll
            for (int mi = 0; mi < 4; mi++) {
                const uint32_t off = (uint32_t)((wm + mi * 16 + l15) * LDSR + kk + khalf) * 2;
                ldsm_x4(ah[mi], sAh + off);
                ldsm_x4(al[mi], sAl + off);
            }
            // --- Bh terms: AhBh + AlBh
            #pragma unroll
            for (int np = 0; np < 4; np++) {
                uint32_t t[4];
                ldsm_x4(t, sBh + (uint32_t)((wn + np * 16 + l15) * LDSR + kk + khalf) * 2);
                bfr[2 * np][0] = t[0]; bfr[2 * np][1] = t[2];
                bfr[2 * np + 1][0] = t[1]; bfr[2 * np + 1][1] = t[3];
            }
            #pragma unroll
            for (int mi = 0; mi < 4; mi++)
                #pragma unroll
                for (int nt = 0; nt < 8; nt++)
                    mma16816(acc[mi][nt], ah[mi], bfr[nt]);
            #pragma unroll
            for (int mi = 0; mi < 4; mi++)
                #pragma unroll
                for (int nt = 0; nt < 8; nt++)
                    mma16816(acc[mi][nt], al[mi], bfr[nt]);
            // --- Bl term: AhBl
            #pragma unroll
            for (int np = 0; np < 4; np++) {
                uint32_t t[4];
                ldsm_x4(t, sBl + (uint32_t)((wn + np * 16 + l15) * LDSR + kk + khalf) * 2);
                bfr[2 * np][0] = t[0]; bfr[2 * np][1] = t[2];
                bfr[2 * np + 1][0] = t[1]; bfr[2 * np + 1][1] = t[3];
            }
            #pragma unroll
            for (int mi = 0; mi < 4; mi++)
                #pragma unroll
                for (int nt = 0; nt < 8; nt++)
                    mma16816(acc[mi][nt], ah[mi], bfr[nt]);
        }
        __syncthreads();
    }

    // ---- epilogue
    if (Chi) {
        #pragma unroll
        for (int mi = 0; mi < 4; mi++) {
            const int r0 = bm + wm + mi * 16 + (lane >> 2);
            #pragma unroll
            for (int nt = 0; nt < 8; nt++) {
                const int c0 = bn + wn + nt * 8 + 2 * (lane & 3);
                uint32_t lo0, lo1;
                uint32_t hi0 = packsplit(acc[mi][nt][0] * cscale, acc[mi][nt][1] * cscale, lo0);
                uint32_t hi1 = packsplit(acc[mi][nt][2] * cscale, acc[mi][nt][3] * cscale, lo1);
                *(uint32_t*)(Chi + (size_t)r0 * N + c0)       = hi0;
                *(uint32_t*)(Clo + (size_t)r0 * N + c0)       = lo0;
                *(uint32_t*)(Chi + (size_t)(r0 + 8) * N + c0) = hi1;
                *(uint32_t*)(Clo + (size_t)(r0 + 8) * N + c0) = lo1;
            }
        }
    } else {
        #pragma unroll
        for (int mi = 0; mi < 4; mi++) {
            const int r0 = bm + wm + mi * 16 + (lane >> 2);
            #pragma unroll
            for (int nt = 0; nt < 8; nt++) {
                const int c0 = bn + wn + nt * 8 + 2 * (lane & 3);
                *(float2*)(C + (size_t)r0 * N + c0)       = make_float2(acc[mi][nt][0], acc[mi][nt][1]);
                *(float2*)(C + (size_t)(r0 + 8) * N + c0) = make_float2(acc[mi][nt][2], acc[mi][nt][3]);
            }
        }
    }
}

// ---------------------------------------------------------------------------
// Tensor-core flash attention, hi/lo split, log2-domain softmax.
// KV fused buffer [MROWS, 1024]: K at col kvh*64, V at col 512 + kvh*64.
// Epilogue writes hi/lo bf16 directly (feeds the O-projection GEMM).
// ---------------------------------------------------------------------------
#define ATT_TILE_BYTES 8192
#define ATT_BUF_BYTES  (4 * ATT_TILE_BYTES)
#define ATT_SMEM       (2 * ATT_BUF_BYTES)

__global__ void __launch_bounds__(256) flash_attn_mma(
    const __nv_bfloat16* __restrict__ Qh, const __nv_bfloat16* __restrict__ Ql,
    const __nv_bfloat16* __restrict__ KVh, const __nv_bfloat16* __restrict__ KVl,
    __nv_bfloat16* __restrict__ AOh, __nv_bfloat16* __restrict__ AOl)
{
    extern __shared__ __nv_bfloat16 smem[];
    const uint32_t sbase = smem_u32(smem);

    const int b    = blockIdx.z;
    const int h    = blockIdx.y;
    const int kvh  = h >> 2;
    const int tid  = threadIdx.x;
    const int lane = tid & 31;
    const int w    = tid >> 5;
    const int qrow = blockIdx.x * 128 + w * 16;

    uint32_t qf[2][4][4];
    {
        const size_t base = ((size_t)(b * S_ + qrow + (lane >> 2))) * DMODEL + h * HD + (lane & 3) * 2;
        #pragma unroll
        for (int kt = 0; kt < 4; kt++) {
            const size_t c = base + kt * 16;
            qf[0][kt][0] = *(const uint32_t*)(Qh + c);
            qf[0][kt][1] = *(const uint32_t*)(Qh + c + 8 * DMODEL);
            qf[0][kt][2] = *(const uint32_t*)(Qh + c + 8);
            qf[0][kt][3] = *(const uint32_t*)(Qh + c + 8 * DMODEL + 8);
            qf[1][kt][0] = *(const uint32_t*)(Ql + c);
            qf[1][kt][1] = *(const uint32_t*)(Ql + c + 8 * DMODEL);
            qf[1][kt][2] = *(const uint32_t*)(Ql + c + 8);
            qf[1][kt][3] = *(const uint32_t*)(Ql + c + 8 * DMODEL + 8);
        }
    }

    float o[8][4];
    #pragma unroll
    for (int nt = 0; nt < 8; nt++)
        #pragma unroll
        for (int r = 0; r < 4; r++) o[nt][r] = 0.0f;
    float m0 = -1e30f, m1 = -1e30f, l0 = 0.0f, l1 = 0.0f;

    const size_t kvbase = (size_t)b * S_ * KVD2 + kvh * HD;
    const __nv_bfloat16* gsrc[4] = {
        KVh + kvbase, KVl + kvbase,                    // K hi, lo
        KVh + kvbase + KVDIM, KVl + kvbase + KVDIM };  // V hi, lo
    const int lrow = tid >> 2;
    const int lc   = tid & 3;

    auto load_tiles = [&](int buf, int lt) {
        #pragma unroll
        for (int t = 0; t < 4; t++) {
            const __nv_bfloat16* src = gsrc[t] + (size_t)(lt * 64 + lrow) * KVD2;
            uint32_t dbase = sbase + buf * ATT_BUF_BYTES + t * ATT_TILE_BYTES;
            cp16(dbase + SW(lrow * 128 + lc * 16), src + lc * 8);
            cp16(dbase + SW(lrow * 128 + (lc + 4) * 16), src + (lc + 4) * 8);
        }
    };

    load_tiles(0, 0);
    asm volatile("cp.async.commit_group;\n");

    const int l7  = lane & 7;
    const int l15 = lane & 15;
    const int khalf = ((lane >> 3) & 1) * 16;

    for (int lt = 0; lt < S_ / 64; lt++) {
        const int cur = lt & 1;
        if (lt + 1 < S_ / 64) load_tiles(1 - cur, lt + 1);
        asm volatile("cp.async.commit_group;\n");
        asm volatile("cp.async.wait_group 1;\n");
        __syncthreads();

        const uint32_t tb = sbase + cur * ATT_BUF_BYTES;

        float s[8][4];
        #pragma unroll
        for (int nt = 0; nt < 8; nt++)
            #pragma unroll
            for (int r = 0; r < 4; r++) s[nt][r] = 0.0f;

        #pragma unroll
        for (int nt = 0; nt < 8; nt++) {
            #pragma unroll
            for (int kt = 0; kt < 4; kt++) {
                const uint32_t inner = (uint32_t)((nt * 8 + l7) * 128 + kt * 32 + khalf);
                uint32_t bh[2], bl[2];
                ldsm_x2(bh[0], bh[1], tb + 0 * ATT_TILE_BYTES + SW(inner));
                ldsm_x2(bl[0], bl[1], tb + 1 * ATT_TILE_BYTES + SW(inner));
                mma16816(s[nt], qf[0][kt], bh);
                mma16816(s[nt], qf[0][kt], bl);
                mma16816(s[nt], qf[1][kt], bh);
            }
        }

        float mx0 = -1e30f, mx1 = -1e30f;
        #pragma unroll
        for (int nt = 0; nt < 8; nt++) {
            mx0 = fmaxf(mx0, fmaxf(s[nt][0], s[nt][1]));
            mx1 = fmaxf(mx1, fmaxf(s[nt][2], s[nt][3]));
        }
        mx0 = fmaxf(mx0, __shfl_xor_sync(0xffffffffu, mx0, 1));
        mx0 = fmaxf(mx0, __shfl_xor_sync(0xffffffffu, mx0, 2));
        mx1 = fmaxf(mx1, __shfl_xor_sync(0xffffffffu, mx1, 1));
        mx1 = fmaxf(mx1, __shfl_xor_sync(0xffffffffu, mx1, 2));
        const float mn0 = fmaxf(m0, mx0), mn1 = fmaxf(m1, mx1);
        const float sc0 = fexp2(m0 - mn0), sc1 = fexp2(m1 - mn1);
        m0 = mn0; m1 = mn1;
        l0 *= sc0; l1 *= sc1;
        #pragma unroll
        for (int nt = 0; nt < 8; nt++) {
            o[nt][0] *= sc0; o[nt][1] *= sc0; o[nt][2] *= sc1; o[nt][3] *= sc1;
        }
        #pragma unroll
        for (int nt = 0; nt < 8; nt++) {
            float p0 = fexp2(s[nt][0] - m0), p1 = fexp2(s[nt][1] - m0);
            float p2 = fexp2(s[nt][2] - m1), p3 = fexp2(s[nt][3] - m1);
            l0 += p0 + p1; l1 += p2 + p3;
            s[nt][0] = p0; s[nt][1] = p1; s[nt][2] = p2; s[nt][3] = p3;
        }

        uint32_t ph_[4][4], pl_[4][4];
        #pragma unroll
        for (int lk = 0; lk < 4; lk++) {
            ph_[lk][0] = packsplit(s[2*lk][0],   s[2*lk][1],   pl_[lk][0]);
            ph_[lk][1] = packsplit(s[2*lk][2],   s[2*lk][3],   pl_[lk][1]);
            ph_[lk][2] = packsplit(s[2*lk+1][0], s[2*lk+1][1], pl_[lk][2]);
            ph_[lk][3] = packsplit(s[2*lk+1][2], s[2*lk+1][3], pl_[lk][3]);
        }

        #pragma unroll
        for (int nt = 0; nt < 8; nt++) {
            #pragma unroll
            for (int lk = 0; lk < 4; lk++) {
                const uint32_t inner = (uint32_t)((lk * 16 + l15) * 128 + nt * 16);
                uint32_t vh[2], vl[2];
                ldsm_x2_t(vh[0], vh[1], tb + 2 * ATT_TILE_BYTES + SW(inner));
                ldsm_x2_t(vl[0], vl[1], tb + 3 * ATT_TILE_BYTES + SW(inner));
                mma16816(o[nt], ph_[lk], vh);
                mma16816(o[nt], ph_[lk], vl);
                mma16816(o[nt], pl_[lk], vh);
            }
        }
        __syncthreads();
    }

    l0 += __shfl_xor_sync(0xffffffffu, l0, 1);
    l0 += __shfl_xor_sync(0xffffffffu, l0, 2);
    l1 += __shfl_xor_sync(0xffffffffu, l1, 1);
    l1 += __shfl_xor_sync(0xffffffffu, l1, 2);
    const float inv0 = 1.0f / l0, inv1 = 1.0f / l1;

    const size_t ro = ((size_t)(b * S_ + qrow + (lane >> 2))) * DMODEL + h * HD + (lane & 3) * 2;
    #pragma unroll
    for (int nt = 0; nt < 8; nt++) {
        uint32_t lo0, lo1;
        uint32_t hi0 = packsplit(o[nt][0] * inv0, o[nt][1] * inv0, lo0);
        uint32_t hi1 = packsplit(o[nt][2] * inv1, o[nt][3] * inv1, lo1);
        *(uint32_t*)(AOh + ro + nt * 8)              = hi0;
        *(uint32_t*)(AOl + ro + nt * 8)              = lo0;
        *(uint32_t*)(AOh + ro + nt * 8 + 8 * DMODEL) = hi1;
        *(uint32_t*)(AOl + ro + nt * 8 + 8 * DMODEL) = lo1;
    }
}

// ---------------------------------------------------------------------------
// Launch
// ---------------------------------------------------------------------------
extern "C" void kernel_launch(void* const* d_in, const int* in_sizes, int n_in,
                              void* d_out, int out_size)
{
    const float* h_bsd = (const float*)d_in[0];
    const float* w_q   = (const float*)d_in[1];
    const float* w_k   = (const float*)d_in[2];
    const float* w_v   = (const float*)d_in[3];
    const float* w_o   = (const float*)d_in[4];
    float* out = (float*)d_out;

    __nv_bfloat16 *Xh, *Xl, *Wqh, *Wql, *Wkvh, *Wkvl, *Woh, *Wol;
    __nv_bfloat16 *Qh, *Ql, *KVh, *KVl, *AOh, *AOl;
    cudaGetSymbolAddress((void**)&Xh, g_Xh);   cudaGetSymbolAddress((void**)&Xl, g_Xl);
    cudaGetSymbolAddress((void**)&Wqh, g_Wqh); cudaGetSymbolAddress((void**)&Wql, g_Wql);
    cudaGetSymbolAddress((void**)&Wkvh, g_Wkvh); cudaGetSymbolAddress((void**)&Wkvl, g_Wkvl);
    cudaGetSymbolAddress((void**)&Woh, g_Woh); cudaGetSymbolAddress((void**)&Wol, g_Wol);
    cudaGetSymbolAddress((void**)&Qh, g_Qh);   cudaGetSymbolAddress((void**)&Ql, g_Ql);
    cudaGetSymbolAddress((void**)&KVh, g_KVh); cudaGetSymbolAddress((void**)&KVl, g_KVl);
    cudaGetSymbolAddress((void**)&AOh, g_AOh); cudaGetSymbolAddress((void**)&AOl, g_AOl);

    static int attr_set = 0;
    if (!attr_set) {
        cudaFuncSetAttribute(flash_attn_mma,
                             cudaFuncAttributeMaxDynamicSharedMemorySize, ATT_SMEM);
        cudaFuncSetAttribute(gemm_split,
                             cudaFuncAttributeMaxDynamicSharedMemorySize, GEMM_SMEM);
        attr_set = 1;
    }

    const int CV = 256;
    split2_bf16<<<512, CV>>>(h_bsd, Xh, Xl, MROWS * DMODEL / 4);
    split2_bf16<<<512, CV>>>(w_q, Wqh, Wql, DMODEL * DMODEL / 4);
    split2_bf16<<<256, CV>>>(w_k, Wkvh, Wkvl, KVDIM * DMODEL / 4);
    split2_bf16<<<256, CV>>>(w_v, Wkvh + (size_t)KVDIM * DMODEL,
                             Wkvl + (size_t)KVDIM * DMODEL, KVDIM * DMODEL / 4);
    split2_bf16<<<512, CV>>>(w_o, Woh, Wol, DMODEL * DMODEL / 4);

    // Q projection (scaled by 1/sqrt(d)*log2 e), fused KV projection
    gemm_split<<<dim3(DMODEL / TCN, MROWS / TCM), 256, GEMM_SMEM>>>(
        Xh, Xl, Wqh, Wql, nullptr, Qh, Ql, QSCALE, MROWS, DMODEL, DMODEL);
    gemm_split<<<dim3(KVD2 / TCN, MROWS / TCM), 256, GEMM_SMEM>>>(
        Xh, Xl, Wkvh, Wkvl, nullptr, KVh, KVl, 1.0f, MROWS, KVD2, DMODEL);

    flash_attn_mma<<<dim3(S_ / 128, NQH, B_), 256, ATT_SMEM>>>(
        Qh, Ql, KVh, KVl, AOh, AOl);

    gemm_split<<<dim3(DMODEL / TCN, MROWS / TCM), 256, GEMM_SMEM>>>(
        AOh, AOl, Woh, Wol, out, nullptr, nullptr, 1.0f, MROWS, DMODEL, DMODEL);
}

// round 11
// speedup vs baseline: 3.3013x; 1.1125x over previous
#include <cuda_runtime.h>
#include <cuda_bf16.h>
#include <math.h>
#include <stdint.h>

// Problem constants
#define B_      2
#define S_      2048
#define DMODEL  2048
#define NQH     32
#define NKVH    8
#define HD      64
#define KVDIM   (NKVH * HD)   // 512
#define KVD2    (2 * KVDIM)   // 1024 (K and V fused)
#define MROWS   (B_ * S_)     // 4096

// ---------------------------------------------------------------------------
// Scratch (__device__ globals; no allocation allowed)
// ---------------------------------------------------------------------------
__device__ __nv_bfloat16 g_Xh [MROWS * DMODEL],  g_Xl [MROWS * DMODEL];
__device__ __nv_bfloat16 g_Wqh[DMODEL * DMODEL], g_Wql[DMODEL * DMODEL];
__device__ __nv_bfloat16 g_Wkvh[KVD2 * DMODEL],  g_Wkvl[KVD2 * DMODEL];
__device__ __nv_bfloat16 g_Woh[DMODEL * DMODEL], g_Wol[DMODEL * DMODEL];
__device__ __nv_bfloat16 g_Qh [MROWS * DMODEL],  g_Ql [MROWS * DMODEL];
__device__ __nv_bfloat16 g_KVh[MROWS * KVD2],    g_KVl[MROWS * KVD2];
__device__ __nv_bfloat16 g_AOh[MROWS * DMODEL],  g_AOl[MROWS * DMODEL];

// ---------------------------------------------------------------------------
// helpers
// ---------------------------------------------------------------------------
__device__ __forceinline__ uint32_t smem_u32(const void* p) {
    return (uint32_t)__cvta_generic_to_shared(p);
}

__device__ __forceinline__ uint32_t packsplit(float a, float b, uint32_t& lo) {
    __nv_bfloat16 ha = __float2bfloat16(a), hb = __float2bfloat16(b);
    __nv_bfloat16 la = __float2bfloat16(a - __bfloat162float(ha));
    __nv_bfloat16 lb = __float2bfloat16(b - __bfloat162float(hb));
    lo = ((uint32_t)__bfloat16_as_ushort(lb) << 16) | (uint32_t)__bfloat16_as_ushort(la);
    return ((uint32_t)__bfloat16_as_ushort(hb) << 16) | (uint32_t)__bfloat16_as_ushort(ha);
}

__device__ __forceinline__ float fexp2(float x) {
    float r;
    asm("ex2.approx.f32 %0, %1;" : "=f"(r) : "f"(x));
    return r;
}

__device__ __forceinline__ void mma16816(float* c, const uint32_t* a, const uint32_t* b) {
    asm volatile(
        "mma.sync.aligned.m16n8k16.row.col.f32.bf16.bf16.f32 "
        "{%0,%1,%2,%3}, {%4,%5,%6,%7}, {%8,%9}, {%0,%1,%2,%3};"
        : "+f"(c[0]), "+f"(c[1]), "+f"(c[2]), "+f"(c[3])
        : "r"(a[0]), "r"(a[1]), "r"(a[2]), "r"(a[3]), "r"(b[0]), "r"(b[1]));
}

__device__ __forceinline__ void ldsm_x4(uint32_t* r, uint32_t addr) {
    asm volatile("ldmatrix.sync.aligned.m8n8.x4.shared.b16 {%0,%1,%2,%3}, [%4];"
                 : "=r"(r[0]), "=r"(r[1]), "=r"(r[2]), "=r"(r[3]) : "r"(addr));
}
__device__ __forceinline__ void ldsm_x2(uint32_t& r0, uint32_t& r1, uint32_t addr) {
    asm volatile("ldmatrix.sync.aligned.m8n8.x2.shared.b16 {%0,%1}, [%2];"
                 : "=r"(r0), "=r"(r1) : "r"(addr));
}
__device__ __forceinline__ void ldsm_x2_t(uint32_t& r0, uint32_t& r1, uint32_t addr) {
    asm volatile("ldmatrix.sync.aligned.m8n8.x2.trans.shared.b16 {%0,%1}, [%2];"
                 : "=r"(r0), "=r"(r1) : "r"(addr));
}

#define SW(a) ((a) ^ (((a) >> 3) & 0x70))

__device__ __forceinline__ void cp16(uint32_t d, const void* s) {
    asm volatile("cp.async.cg.shared.global [%0], [%1], 16;\n" :: "r"(d), "l"(s));
}

// softmax scale: 1/sqrt(64) * log2(e)
#define QSCALE 0.18033688011112042f

// ---------------------------------------------------------------------------
// fp32 -> (hi, lo) bf16 buffers.
// ---------------------------------------------------------------------------
__global__ void split2_bf16(const float* __restrict__ X,
                            __nv_bfloat16* __restrict__ Yh,
                            __nv_bfloat16* __restrict__ Yl, int total4)
{
    for (int i = blockIdx.x * blockDim.x + threadIdx.x; i < total4;
         i += gridDim.x * blockDim.x) {
        const int idx = i * 4;
        float4 x = *(const float4*)(X + idx);
        uint32_t lo0, lo1;
        uint32_t hi0 = packsplit(x.x, x.y, lo0);
        uint32_t hi1 = packsplit(x.z, x.w, lo1);
        *(uint2*)(Yh + idx) = make_uint2(hi0, hi1);
        *(uint2*)(Yl + idx) = make_uint2(lo0, lo1);
    }
}

// ---------------------------------------------------------------------------
// Split-precision GEMM on mma.sync:
//   C[M,N] = (Ah+Al)[M,K] * (Bh+Bl)[N,K]^T  via  AhBh + AhBl + AlBh
// CTA 128x256, 16 warps (4M x 4N) at 32x64 each, BK=32, 2-stage cp.async.
// 512 threads -> 4 warps/SMSP for HMMA latency hiding.
// ---------------------------------------------------------------------------
#define TCM 128
#define TCN 256
#define TCK 32
#define LDSR 40                         // 32 + 8 pad (elements)
#define SA_BYTES (TCM * LDSR * 2)       // 10240
#define SB_BYTES (TCN * LDSR * 2)       // 20480
#define STAGE_BYTES (2 * SA_BYTES + 2 * SB_BYTES)   // 61440
#define GEMM_SMEM (2 * STAGE_BYTES)                 // 122880

__global__ void __launch_bounds__(512, 1) gemm_split(
    const __nv_bfloat16* __restrict__ Ah, const __nv_bfloat16* __restrict__ Al,
    const __nv_bfloat16* __restrict__ Bh, const __nv_bfloat16* __restrict__ Bl,
    float* __restrict__ C,
    __nv_bfloat16* __restrict__ Chi, __nv_bfloat16* __restrict__ Clo,
    float cscale, int M, int N, int Kk)
{
    extern __shared__ __align__(128) char sm[];
    const uint32_t sb = smem_u32(sm);

    const int tid  = threadIdx.x;
    const int lane = tid & 31;
    const int w    = tid >> 5;          // 0..15
    const int wm   = (w & 3) * 32;      // M slab (4 x 32)
    const int wn   = (w >> 2) * 64;     // N slab (4 x 64)
    const int bm   = blockIdx.y * TCM;
    const int bn   = blockIdx.x * TCN;

    float acc[2][8][4];
    #pragma unroll
    for (int mi = 0; mi < 2; mi++)
        #pragma unroll
        for (int nt = 0; nt < 8; nt++)
            #pragma unroll
            for (int r = 0; r < 4; r++) acc[mi][nt][r] = 0.0f;

    // load mapping (512 threads):
    // A: 128 rows x 4 chunks(16B) -> thread t: row t>>2, chunk t&3   (1 cp16 x hi/lo)
    // B: 256 rows x 4 chunks      -> thread t: row t>>1, chunks (t&1)*2 + {0,1}
    const int arow = tid >> 2, acp = (tid & 3) * 8;      // elements
    const int brow = tid >> 1, bcp = (tid & 1) * 16;     // elements
    const __nv_bfloat16* gAh = Ah + (size_t)(bm + arow) * Kk + acp;
    const __nv_bfloat16* gAl = Al + (size_t)(bm + arow) * Kk + acp;
    const __nv_bfloat16* gBh = Bh + (size_t)(bn + brow) * Kk + bcp;
    const __nv_bfloat16* gBl = Bl + (size_t)(bn + brow) * Kk + bcp;
    const uint32_t aso = (uint32_t)(arow * LDSR + acp) * 2;
    const uint32_t bso = (uint32_t)(brow * LDSR + bcp) * 2;

    auto load_stage = [&](int buf, int kt) {
        const uint32_t st = sb + buf * STAGE_BYTES;
        const int k0 = kt * TCK;
        cp16(st + aso, gAh + k0);
        cp16(st + SA_BYTES + aso, gAl + k0);
        #pragma unroll
        for (int j = 0; j < 2; j++) {
            cp16(st + 2 * SA_BYTES + bso + j * 16, gBh + k0 + j * 8);
            cp16(st + 2 * SA_BYTES + SB_BYTES + bso + j * 16, gBl + k0 + j * 8);
        }
    };

    const int NT = Kk / TCK;
    load_stage(0, 0);
    asm volatile("cp.async.commit_group;\n");

    const int l15 = lane & 15;
    const int khalf = (lane >> 4) << 3;

    for (int kt = 0; kt < NT; kt++) {
        const int cur = kt & 1;
        if (kt + 1 < NT) {
            load_stage(1 - cur, kt + 1);
            asm volatile("cp.async.commit_group;\n");
            asm volatile("cp.async.wait_group 1;\n");
        } else {
            asm volatile("cp.async.wait_group 0;\n");
        }
        __syncthreads();

        const uint32_t sAh = sb + cur * STAGE_BYTES;
        const uint32_t sAl = sAh + SA_BYTES;
        const uint32_t sBh = sAh + 2 * SA_BYTES;
        const uint32_t sBl = sBh + SB_BYTES;

        #pragma unroll
        for (int kk = 0; kk < TCK; kk += 16) {
            uint32_t ah[2][4], al[2][4], bfr[8][2];
            #pragma unroll
            for (int mi = 0; mi < 2; mi++) {
                const uint32_t off = (uint32_t)((wm + mi * 16 + l15) * LDSR + kk + khalf) * 2;
                ldsm_x4(ah[mi], sAh + off);
                ldsm_x4(al[mi], sAl + off);
            }
            // --- Bh terms: AhBh + AlBh
            #pragma unroll
            for (int np = 0; np < 4; np++) {
                uint32_t t[4];
                ldsm_x4(t, sBh + (uint32_t)((wn + np * 16 + l15) * LDSR + kk + khalf) * 2);
                bfr[2 * np][0] = t[0]; bfr[2 * np][1] = t[2];
                bfr[2 * np + 1][0] = t[1]; bfr[2 * np + 1][1] = t[3];
            }
            #pragma unroll
            for (int mi = 0; mi < 2; mi++)
                #pragma unroll
                for (int nt = 0; nt < 8; nt++)
                    mma16816(acc[mi][nt], ah[mi], bfr[nt]);
            #pragma unroll
            for (int mi = 0; mi < 2; mi++)
                #pragma unroll
                for (int nt = 0; nt < 8; nt++)
                    mma16816(acc[mi][nt], al[mi], bfr[nt]);
            // --- Bl term: AhBl
            #pragma unroll
            for (int np = 0; np < 4; np++) {
                uint32_t t[4];
                ldsm_x4(t, sBl + (uint32_t)((wn + np * 16 + l15) * LDSR + kk + khalf) * 2);
                bfr[2 * np][0] = t[0]; bfr[2 * np][1] = t[2];
                bfr[2 * np + 1][0] = t[1]; bfr[2 * np + 1][1] = t[3];
            }
            #pragma unroll
            for (int mi = 0; mi < 2; mi++)
                #pragma unroll
                for (int nt = 0; nt < 8; nt++)
                    mma16816(acc[mi][nt], ah[mi], bfr[nt]);
        }
        __syncthreads();
    }

    // ---- epilogue
    if (Chi) {
        #pragma unroll
        for (int mi = 0; mi < 2; mi++) {
            const int r0 = bm + wm + mi * 16 + (lane >> 2);
            #pragma unroll
            for (int nt = 0; nt < 8; nt++) {
                const int c0 = bn + wn + nt * 8 + 2 * (lane & 3);
                uint32_t lo0, lo1;
                uint32_t hi0 = packsplit(acc[mi][nt][0] * cscale, acc[mi][nt][1] * cscale, lo0);
                uint32_t hi1 = packsplit(acc[mi][nt][2] * cscale, acc[mi][nt][3] * cscale, lo1);
                *(uint32_t*)(Chi + (size_t)r0 * N + c0)       = hi0;
                *(uint32_t*)(Clo + (size_t)r0 * N + c0)       = lo0;
                *(uint32_t*)(Chi + (size_t)(r0 + 8) * N + c0) = hi1;
                *(uint32_t*)(Clo + (size_t)(r0 + 8) * N + c0) = lo1;
            }
        }
    } else {
        #pragma unroll
        for (int mi = 0; mi < 2; mi++) {
            const int r0 = bm + wm + mi * 16 + (lane >> 2);
            #pragma unroll
            for (int nt = 0; nt < 8; nt++) {
                const int c0 = bn + wn + nt * 8 + 2 * (lane & 3);
                *(float2*)(C + (size_t)r0 * N + c0)       = make_float2(acc[mi][nt][0], acc[mi][nt][1]);
                *(float2*)(C + (size_t)(r0 + 8) * N + c0) = make_float2(acc[mi][nt][2], acc[mi][nt][3]);
            }
        }
    }
}

// ---------------------------------------------------------------------------
// Tensor-core flash attention, hi/lo split, log2-domain softmax (unchanged).
// ---------------------------------------------------------------------------
#define ATT_TILE_BYTES 8192
#define ATT_BUF_BYTES  (4 * ATT_TILE_BYTES)
#define ATT_SMEM       (2 * ATT_BUF_BYTES)

__global__ void __launch_bounds__(256) flash_attn_mma(
    const __nv_bfloat16* __restrict__ Qh, const __nv_bfloat16* __restrict__ Ql,
    const __nv_bfloat16* __restrict__ KVh, const __nv_bfloat16* __restrict__ KVl,
    __nv_bfloat16* __restrict__ AOh, __nv_bfloat16* __restrict__ AOl)
{
    extern __shared__ __nv_bfloat16 smem[];
    const uint32_t sbase = smem_u32(smem);

    const int b    = blockIdx.z;
    const int h    = blockIdx.y;
    const int kvh  = h >> 2;
    const int tid  = threadIdx.x;
    const int lane = tid & 31;
    const int w    = tid >> 5;
    const int qrow = blockIdx.x * 128 + w * 16;

    uint32_t qf[2][4][4];
    {
        const size_t base = ((size_t)(b * S_ + qrow + (lane >> 2))) * DMODEL + h * HD + (lane & 3) * 2;
        #pragma unroll
        for (int kt = 0; kt < 4; kt++) {
            const size_t c = base + kt * 16;
            qf[0][kt][0] = *(const uint32_t*)(Qh + c);
            qf[0][kt][1] = *(const uint32_t*)(Qh + c + 8 * DMODEL);
            qf[0][kt][2] = *(const uint32_t*)(Qh + c + 8);
            qf[0][kt][3] = *(const uint32_t*)(Qh + c + 8 * DMODEL + 8);
            qf[1][kt][0] = *(const uint32_t*)(Ql + c);
            qf[1][kt][1] = *(const uint32_t*)(Ql + c + 8 * DMODEL);
            qf[1][kt][2] = *(const uint32_t*)(Ql + c + 8);
            qf[1][kt][3] = *(const uint32_t*)(Ql + c + 8 * DMODEL + 8);
        }
    }

    float o[8][4];
    #pragma unroll
    for (int nt = 0; nt < 8; nt++)
        #pragma unroll
        for (int r = 0; r < 4; r++) o[nt][r] = 0.0f;
    float m0 = -1e30f, m1 = -1e30f, l0 = 0.0f, l1 = 0.0f;

    const size_t kvbase = (size_t)b * S_ * KVD2 + kvh * HD;
    const __nv_bfloat16* gsrc[4] = {
        KVh + kvbase, KVl + kvbase,
        KVh + kvbase + KVDIM, KVl + kvbase + KVDIM };
    const int lrow = tid >> 2;
    const int lc   = tid & 3;

    auto load_tiles = [&](int buf, int lt) {
        #pragma unroll
        for (int t = 0; t < 4; t++) {
            const __nv_bfloat16* src = gsrc[t] + (size_t)(lt * 64 + lrow) * KVD2;
            uint32_t dbase = sbase + buf * ATT_BUF_BYTES + t * ATT_TILE_BYTES;
            cp16(dbase + SW(lrow * 128 + lc * 16), src + lc * 8);
            cp16(dbase + SW(lrow * 128 + (lc + 4) * 16), src + (lc + 4) * 8);
        }
    };

    load_tiles(0, 0);
    asm volatile("cp.async.commit_group;\n");

    const int l7  = lane & 7;
    const int l15 = lane & 15;
    const int khalf = ((lane >> 3) & 1) * 16;

    for (int lt = 0; lt < S_ / 64; lt++) {
        const int cur = lt & 1;
        if (lt + 1 < S_ / 64) load_tiles(1 - cur, lt + 1);
        asm volatile("cp.async.commit_group;\n");
        asm volatile("cp.async.wait_group 1;\n");
        __syncthreads();

        const uint32_t tb = sbase + cur * ATT_BUF_BYTES;

        float s[8][4];
        #pragma unroll
        for (int nt = 0; nt < 8; nt++)
            #pragma unroll
            for (int r = 0; r < 4; r++) s[nt][r] = 0.0f;

        #pragma unroll
        for (int nt = 0; nt < 8; nt++) {
            #pragma unroll
            for (int kt = 0; kt < 4; kt++) {
                const uint32_t inner = (uint32_t)((nt * 8 + l7) * 128 + kt * 32 + khalf);
                uint32_t bh[2], bl[2];
                ldsm_x2(bh[0], bh[1], tb + 0 * ATT_TILE_BYTES + SW(inner));
                ldsm_x2(bl[0], bl[1], tb + 1 * ATT_TILE_BYTES + SW(inner));
                mma16816(s[nt], qf[0][kt], bh);
                mma16816(s[nt], qf[0][kt], bl);
                mma16816(s[nt], qf[1][kt], bh);
            }
        }

        float mx0 = -1e30f, mx1 = -1e30f;
        #pragma unroll
        for (int nt = 0; nt < 8; nt++) {
            mx0 = fmaxf(mx0, fmaxf(s[nt][0], s[nt][1]));
            mx1 = fmaxf(mx1, fmaxf(s[nt][2], s[nt][3]));
        }
        mx0 = fmaxf(mx0, __shfl_xor_sync(0xffffffffu, mx0, 1));
        mx0 = fmaxf(mx0, __shfl_xor_sync(0xffffffffu, mx0, 2));
        mx1 = fmaxf(mx1, __shfl_xor_sync(0xffffffffu, mx1, 1));
        mx1 = fmaxf(mx1, __shfl_xor_sync(0xffffffffu, mx1, 2));
        const float mn0 = fmaxf(m0, mx0), mn1 = fmaxf(m1, mx1);
        const float sc0 = fexp2(m0 - mn0), sc1 = fexp2(m1 - mn1);
        m0 = mn0; m1 = mn1;
        l0 *= sc0; l1 *= sc1;
        #pragma unroll
        for (int nt = 0; nt < 8; nt++) {
            o[nt][0] *= sc0; o[nt][1] *= sc0; o[nt][2] *= sc1; o[nt][3] *= sc1;
        }
        #pragma unroll
        for (int nt = 0; nt < 8; nt++) {
            float p0 = fexp2(s[nt][0] - m0), p1 = fexp2(s[nt][1] - m0);
            float p2 = fexp2(s[nt][2] - m1), p3 = fexp2(s[nt][3] - m1);
            l0 += p0 + p1; l1 += p2 + p3;
            s[nt][0] = p0; s[nt][1] = p1; s[nt][2] = p2; s[nt][3] = p3;
        }

        uint32_t ph_[4][4], pl_[4][4];
        #pragma unroll
        for (int lk = 0; lk < 4; lk++) {
            ph_[lk][0] = packsplit(s[2*lk][0],   s[2*lk][1],   pl_[lk][0]);
            ph_[lk][1] = packsplit(s[2*lk][2],   s[2*lk][3],   pl_[lk][1]);
            ph_[lk][2] = packsplit(s[2*lk+1][0], s[2*lk+1][1], pl_[lk][2]);
            ph_[lk][3] = packsplit(s[2*lk+1][2], s[2*lk+1][3], pl_[lk][3]);
        }

        #pragma unroll
        for (int nt = 0; nt < 8; nt++) {
            #pragma unroll
            for (int lk = 0; lk < 4; lk++) {
                const uint32_t inner = (uint32_t)((lk * 16 + l15) * 128 + nt * 16);
                uint32_t vh[2], vl[2];
                ldsm_x2_t(vh[0], vh[1], tb + 2 * ATT_TILE_BYTES + SW(inner));
                ldsm_x2_t(vl[0], vl[1], tb + 3 * ATT_TILE_BYTES + SW(inner));
                mma16816(o[nt], ph_[lk], vh);
                mma16816(o[nt], ph_[lk], vl);
                mma16816(o[nt], pl_[lk], vh);
            }
        }
        __syncthreads();
    }

    l0 += __shfl_xor_sync(0xffffffffu, l0, 1);
    l0 += __shfl_xor_sync(0xffffffffu, l0, 2);
    l1 += __shfl_xor_sync(0xffffffffu, l1, 1);
    l1 += __shfl_xor_sync(0xffffffffu, l1, 2);
    const float inv0 = 1.0f / l0, inv1 = 1.0f / l1;

    const size_t ro = ((size_t)(b * S_ + qrow + (lane >> 2))) * DMODEL + h * HD + (lane & 3) * 2;
    #pragma unroll
    for (int nt = 0; nt < 8; nt++) {
        uint32_t lo0, lo1;
        uint32_t hi0 = packsplit(o[nt][0] * inv0, o[nt][1] * inv0, lo0);
        uint32_t hi1 = packsplit(o[nt][2] * inv1, o[nt][3] * inv1, lo1);
        *(uint32_t*)(AOh + ro + nt * 8)              = hi0;
        *(uint32_t*)(AOl + ro + nt * 8)              = lo0;
        *(uint32_t*)(AOh + ro + nt * 8 + 8 * DMODEL) = hi1;
        *(uint32_t*)(AOl + ro + nt * 8 + 8 * DMODEL) = lo1;
    }
}

// ---------------------------------------------------------------------------
// Launch
// ---------------------------------------------------------------------------
extern "C" void kernel_launch(void* const* d_in, const int* in_sizes, int n_in,
                              void* d_out, int out_size)
{
    const float* h_bsd = (const float*)d_in[0];
    const float* w_q   = (const float*)d_in[1];
    const float* w_k   = (const float*)d_in[2];
    const float* w_v   = (const float*)d_in[3];
    const float* w_o   = (const float*)d_in[4];
    float* out = (float*)d_out;

    __nv_bfloat16 *Xh, *Xl, *Wqh, *Wql, *Wkvh, *Wkvl, *Woh, *Wol;
    __nv_bfloat16 *Qh, *Ql, *KVh, *KVl, *AOh, *AOl;
    cudaGetSymbolAddress((void**)&Xh, g_Xh);   cudaGetSymbolAddress((void**)&Xl, g_Xl);
    cudaGetSymbolAddress((void**)&Wqh, g_Wqh); cudaGetSymbolAddress((void**)&Wql, g_Wql);
    cudaGetSymbolAddress((void**)&Wkvh, g_Wkvh); cudaGetSymbolAddress((void**)&Wkvl, g_Wkvl);
    cudaGetSymbolAddress((void**)&Woh, g_Woh); cudaGetSymbolAddress((void**)&Wol, g_Wol);
    cudaGetSymbolAddress((void**)&Qh, g_Qh);   cudaGetSymbolAddress((void**)&Ql, g_Ql);
    cudaGetSymbolAddress((void**)&KVh, g_KVh); cudaGetSymbolAddress((void**)&KVl, g_KVl);
    cudaGetSymbolAddress((void**)&AOh, g_AOh); cudaGetSymbolAddress((void**)&AOl, g_AOl);

    static int attr_set = 0;
    if (!attr_set) {
        cudaFuncSetAttribute(flash_attn_mma,
                             cudaFuncAttributeMaxDynamicSharedMemorySize, ATT_SMEM);
        cudaFuncSetAttribute(gemm_split,
                             cudaFuncAttributeMaxDynamicSharedMemorySize, GEMM_SMEM);
        attr_set = 1;
    }

    const int CV = 256;
    split2_bf16<<<512, CV>>>(h_bsd, Xh, Xl, MROWS * DMODEL / 4);
    split2_bf16<<<512, CV>>>(w_q, Wqh, Wql, DMODEL * DMODEL / 4);
    split2_bf16<<<256, CV>>>(w_k, Wkvh, Wkvl, KVDIM * DMODEL / 4);
    split2_bf16<<<256, CV>>>(w_v, Wkvh + (size_t)KVDIM * DMODEL,
                             Wkvl + (size_t)KVDIM * DMODEL, KVDIM * DMODEL / 4);
    split2_bf16<<<512, CV>>>(w_o, Woh, Wol, DMODEL * DMODEL / 4);

    gemm_split<<<dim3(DMODEL / TCN, MROWS / TCM), 512, GEMM_SMEM>>>(
        Xh, Xl, Wqh, Wql, nullptr, Qh, Ql, QSCALE, MROWS, DMODEL, DMODEL);
    gemm_split<<<dim3(KVD2 / TCN, MROWS / TCM), 512, GEMM_SMEM>>>(
        Xh, Xl, Wkvh, Wkvl, nullptr, KVh, KVl, 1.0f, MROWS, KVD2, DMODEL);

    flash_attn_mma<<<dim3(S_ / 128, NQH, B_), 256, ATT_SMEM>>>(
        Qh, Ql, KVh, KVl, AOh, AOl);

    gemm_split<<<dim3(DMODEL / TCN, MROWS / TCM), 512, GEMM_SMEM>>>(
        AOh, AOl, Woh, Wol, out, nullptr, nullptr, 1.0f, MROWS, DMODEL, DMODEL);
}

// round 12
// speedup vs baseline: 3.3950x; 1.0284x over previous
#include <cuda_runtime.h>
#include <cuda_bf16.h>
#include <math.h>
#include <stdint.h>

// Problem constants
#define B_      2
#define S_      2048
#define DMODEL  2048
#define NQH     32
#define NKVH    8
#define HD      64
#define KVDIM   (NKVH * HD)   // 512
#define KVD2    (2 * KVDIM)   // 1024 (K and V fused)
#define MROWS   (B_ * S_)     // 4096

// ---------------------------------------------------------------------------
// Scratch (__device__ globals; no allocation allowed)
// ---------------------------------------------------------------------------
__device__ __nv_bfloat16 g_Xh [MROWS * DMODEL],  g_Xl [MROWS * DMODEL];
__device__ __nv_bfloat16 g_Wqh[DMODEL * DMODEL], g_Wql[DMODEL * DMODEL];
__device__ __nv_bfloat16 g_Wkvh[KVD2 * DMODEL],  g_Wkvl[KVD2 * DMODEL];
__device__ __nv_bfloat16 g_Woh[DMODEL * DMODEL], g_Wol[DMODEL * DMODEL];
__device__ __nv_bfloat16 g_Qh [MROWS * DMODEL],  g_Ql [MROWS * DMODEL];
__device__ __nv_bfloat16 g_KVh[MROWS * KVD2],    g_KVl[MROWS * KVD2];
__device__ __nv_bfloat16 g_AOh[MROWS * DMODEL],  g_AOl[MROWS * DMODEL];

// ---------------------------------------------------------------------------
// helpers
// ---------------------------------------------------------------------------
__device__ __forceinline__ uint32_t smem_u32(const void* p) {
    return (uint32_t)__cvta_generic_to_shared(p);
}

__device__ __forceinline__ uint32_t packsplit(float a, float b, uint32_t& lo) {
    __nv_bfloat16 ha = __float2bfloat16(a), hb = __float2bfloat16(b);
    __nv_bfloat16 la = __float2bfloat16(a - __bfloat162float(ha));
    __nv_bfloat16 lb = __float2bfloat16(b - __bfloat162float(hb));
    lo = ((uint32_t)__bfloat16_as_ushort(lb) << 16) | (uint32_t)__bfloat16_as_ushort(la);
    return ((uint32_t)__bfloat16_as_ushort(hb) << 16) | (uint32_t)__bfloat16_as_ushort(ha);
}

__device__ __forceinline__ float fexp2(float x) {
    float r;
    asm("ex2.approx.f32 %0, %1;" : "=f"(r) : "f"(x));
    return r;
}

__device__ __forceinline__ void mma16816(float* c, const uint32_t* a, const uint32_t* b) {
    asm volatile(
        "mma.sync.aligned.m16n8k16.row.col.f32.bf16.bf16.f32 "
        "{%0,%1,%2,%3}, {%4,%5,%6,%7}, {%8,%9}, {%0,%1,%2,%3};"
        : "+f"(c[0]), "+f"(c[1]), "+f"(c[2]), "+f"(c[3])
        : "r"(a[0]), "r"(a[1]), "r"(a[2]), "r"(a[3]), "r"(b[0]), "r"(b[1]));
}
// b-operand given as two regs picked from an ldsm_x4 result
__device__ __forceinline__ void mma2(float* c, const uint32_t* a, uint32_t b0, uint32_t b1) {
    asm volatile(
        "mma.sync.aligned.m16n8k16.row.col.f32.bf16.bf16.f32 "
        "{%0,%1,%2,%3}, {%4,%5,%6,%7}, {%8,%9}, {%0,%1,%2,%3};"
        : "+f"(c[0]), "+f"(c[1]), "+f"(c[2]), "+f"(c[3])
        : "r"(a[0]), "r"(a[1]), "r"(a[2]), "r"(a[3]), "r"(b0), "r"(b1));
}

__device__ __forceinline__ void ldsm_x4(uint32_t* r, uint32_t addr) {
    asm volatile("ldmatrix.sync.aligned.m8n8.x4.shared.b16 {%0,%1,%2,%3}, [%4];"
                 : "=r"(r[0]), "=r"(r[1]), "=r"(r[2]), "=r"(r[3]) : "r"(addr));
}
__device__ __forceinline__ void ldsm_x4_t(uint32_t* r, uint32_t addr) {
    asm volatile("ldmatrix.sync.aligned.m8n8.x4.trans.shared.b16 {%0,%1,%2,%3}, [%4];"
                 : "=r"(r[0]), "=r"(r[1]), "=r"(r[2]), "=r"(r[3]) : "r"(addr));
}

#define SW(a) ((a) ^ (((a) >> 3) & 0x70))

__device__ __forceinline__ void cp16(uint32_t d, const void* s) {
    asm volatile("cp.async.cg.shared.global [%0], [%1], 16;\n" :: "r"(d), "l"(s));
}

// softmax scale: 1/sqrt(64) * log2(e)
#define QSCALE 0.18033688011112042f

// ---------------------------------------------------------------------------
// fp32 -> (hi, lo) bf16 buffers.
// ---------------------------------------------------------------------------
__global__ void split2_bf16(const float* __restrict__ X,
                            __nv_bfloat16* __restrict__ Yh,
                            __nv_bfloat16* __restrict__ Yl, int total4)
{
    for (int i = blockIdx.x * blockDim.x + threadIdx.x; i < total4;
         i += gridDim.x * blockDim.x) {
        const int idx = i * 4;
        float4 x = *(const float4*)(X + idx);
        uint32_t lo0, lo1;
        uint32_t hi0 = packsplit(x.x, x.y, lo0);
        uint32_t hi1 = packsplit(x.z, x.w, lo1);
        *(uint2*)(Yh + idx) = make_uint2(hi0, hi1);
        *(uint2*)(Yl + idx) = make_uint2(lo0, lo1);
    }
}

// ---------------------------------------------------------------------------
// Split-precision GEMM on mma.sync:
//   C[M,N] = (Ah+Al)[M,K] * (Bh+Bl)[N,K]^T  via  AhBh + AhBl + AlBh
// CTA 128x256, 16 warps (4M x 4N) at 32x64 each, TCK=64, SW128-swizzled
// 128-byte-row stages (no padding), 2-stage cp.async.
// ---------------------------------------------------------------------------
#define TCM 128
#define TCN 256
#define TCK 64
// per-stage layout (bytes): Ah 16K | Al 16K | Bh 32K | Bl 32K
#define GA_AL 16384
#define GA_BH 32768
#define GA_BL 65536
#define STAGE_BYTES 98304
#define GEMM_SMEM (2 * STAGE_BYTES)    // 196608

__global__ void __launch_bounds__(512, 1) gemm_split(
    const __nv_bfloat16* __restrict__ Ah, const __nv_bfloat16* __restrict__ Al,
    const __nv_bfloat16* __restrict__ Bh, const __nv_bfloat16* __restrict__ Bl,
    float* __restrict__ C,
    __nv_bfloat16* __restrict__ Chi, __nv_bfloat16* __restrict__ Clo,
    float cscale, int M, int N, int Kk)
{
    extern __shared__ __align__(1024) char sm[];
    const uint32_t sb = smem_u32(sm);

    const int tid  = threadIdx.x;
    const int lane = tid & 31;
    const int w    = tid >> 5;          // 0..15
    const int wm   = (w & 3) * 32;      // M slab (4 x 32)
    const int wn   = (w >> 2) * 64;     // N slab (4 x 64)
    const int bm   = blockIdx.y * TCM;
    const int bn   = blockIdx.x * TCN;

    float acc[2][8][4];
    #pragma unroll
    for (int mi = 0; mi < 2; mi++)
        #pragma unroll
        for (int nt = 0; nt < 8; nt++)
            #pragma unroll
            for (int r = 0; r < 4; r++) acc[mi][nt][r] = 0.0f;

    // load mapping (512 threads, 128B rows = 8 x 16B chunks):
    // A (128 rows): thread t -> row t>>2, chunks (t&3)*2 + {0,1}
    // B (256 rows): thread t -> row t>>1, chunks (t&1)*4 + {0..3}
    const int arow = tid >> 2, ach = (tid & 3) * 2;
    const int brow = tid >> 1, bch = (tid & 1) * 4;
    const __nv_bfloat16* gAh = Ah + (size_t)(bm + arow) * Kk + ach * 8;
    const __nv_bfloat16* gAl = Al + (size_t)(bm + arow) * Kk + ach * 8;
    const __nv_bfloat16* gBh = Bh + (size_t)(bn + brow) * Kk + bch * 8;
    const __nv_bfloat16* gBl = Bl + (size_t)(bn + brow) * Kk + bch * 8;

    auto load_stage = [&](int buf, int kt) {
        const uint32_t st = sb + buf * STAGE_BYTES;
        const int k0 = kt * TCK;
        #pragma unroll
        for (int j = 0; j < 2; j++) {
            const uint32_t d = SW((uint32_t)(arow * 128 + (ach + j) * 16));
            cp16(st + d, gAh + k0 + j * 8);
            cp16(st + GA_AL + d, gAl + k0 + j * 8);
        }
        #pragma unroll
        for (int j = 0; j < 4; j++) {
            const uint32_t d = SW((uint32_t)(brow * 128 + (bch + j) * 16));
            cp16(st + GA_BH + d, gBh + k0 + j * 8);
            cp16(st + GA_BL + d, gBl + k0 + j * 8);
        }
    };

    const int NT = Kk / TCK;
    load_stage(0, 0);
    asm volatile("cp.async.commit_group;\n");

    const int l15 = lane & 15;
    const int colh = (lane >> 4) << 4;   // 0 or 16 bytes (k-half)

    for (int kt = 0; kt < NT; kt++) {
        const int cur = kt & 1;
        if (kt + 1 < NT) {
            load_stage(1 - cur, kt + 1);
            asm volatile("cp.async.commit_group;\n");
            asm volatile("cp.async.wait_group 1;\n");
        } else {
            asm volatile("cp.async.wait_group 0;\n");
        }
        __syncthreads();

        const uint32_t st = sb + cur * STAGE_BYTES;

        #pragma unroll
        for (int kk = 0; kk < 4; kk++) {            // 4 x k16
            const uint32_t colb = (uint32_t)(kk * 32 + colh);
            uint32_t ah[2][4], al[2][4];
            #pragma unroll
            for (int mi = 0; mi < 2; mi++) {
                const uint32_t off = SW((uint32_t)((wm + mi * 16 + l15) * 128) + colb);
                ldsm_x4(ah[mi], st + off);
                ldsm_x4(al[mi], st + GA_AL + off);
            }
            #pragma unroll
            for (int np = 0; np < 4; np++) {
                const uint32_t offb = SW((uint32_t)((wn + np * 16 + l15) * 128) + colb);
                uint32_t t[4];
                ldsm_x4(t, st + GA_BH + offb);
                // AhBh + AlBh
                mma2(acc[0][2*np],   ah[0], t[0], t[2]);
                mma2(acc[0][2*np+1], ah[0], t[1], t[3]);
                mma2(acc[1][2*np],   ah[1], t[0], t[2]);
                mma2(acc[1][2*np+1], ah[1], t[1], t[3]);
                mma2(acc[0][2*np],   al[0], t[0], t[2]);
                mma2(acc[0][2*np+1], al[0], t[1], t[3]);
                mma2(acc[1][2*np],   al[1], t[0], t[2]);
                mma2(acc[1][2*np+1], al[1], t[1], t[3]);
                // AhBl
                ldsm_x4(t, st + GA_BL + offb);
                mma2(acc[0][2*np],   ah[0], t[0], t[2]);
                mma2(acc[0][2*np+1], ah[0], t[1], t[3]);
                mma2(acc[1][2*np],   ah[1], t[0], t[2]);
                mma2(acc[1][2*np+1], ah[1], t[1], t[3]);
            }
        }
        __syncthreads();
    }

    // ---- epilogue
    if (Chi) {
        #pragma unroll
        for (int mi = 0; mi < 2; mi++) {
            const int r0 = bm + wm + mi * 16 + (lane >> 2);
            #pragma unroll
            for (int nt = 0; nt < 8; nt++) {
                const int c0 = bn + wn + nt * 8 + 2 * (lane & 3);
                uint32_t lo0, lo1;
                uint32_t hi0 = packsplit(acc[mi][nt][0] * cscale, acc[mi][nt][1] * cscale, lo0);
                uint32_t hi1 = packsplit(acc[mi][nt][2] * cscale, acc[mi][nt][3] * cscale, lo1);
                *(uint32_t*)(Chi + (size_t)r0 * N + c0)       = hi0;
                *(uint32_t*)(Clo + (size_t)r0 * N + c0)       = lo0;
                *(uint32_t*)(Chi + (size_t)(r0 + 8) * N + c0) = hi1;
                *(uint32_t*)(Clo + (size_t)(r0 + 8) * N + c0) = lo1;
            }
        }
    } else {
        #pragma unroll
        for (int mi = 0; mi < 2; mi++) {
            const int r0 = bm + wm + mi * 16 + (lane >> 2);
            #pragma unroll
            for (int nt = 0; nt < 8; nt++) {
                const int c0 = bn + wn + nt * 8 + 2 * (lane & 3);
                *(float2*)(C + (size_t)r0 * N + c0)       = make_float2(acc[mi][nt][0], acc[mi][nt][1]);
                *(float2*)(C + (size_t)(r0 + 8) * N + c0) = make_float2(acc[mi][nt][2], acc[mi][nt][3]);
            }
        }
    }
}

// ---------------------------------------------------------------------------
// Tensor-core flash attention, hi/lo split, log2-domain softmax.
// All K/V fragment loads via ldsm_x4 (paired n-tiles / col-pairs).
// ---------------------------------------------------------------------------
#define ATT_TILE_BYTES 8192
#define ATT_BUF_BYTES  (4 * ATT_TILE_BYTES)
#define ATT_SMEM       (2 * ATT_BUF_BYTES)

__global__ void __launch_bounds__(256) flash_attn_mma(
    const __nv_bfloat16* __restrict__ Qh, const __nv_bfloat16* __restrict__ Ql,
    const __nv_bfloat16* __restrict__ KVh, const __nv_bfloat16* __restrict__ KVl,
    __nv_bfloat16* __restrict__ AOh, __nv_bfloat16* __restrict__ AOl)
{
    extern __shared__ __nv_bfloat16 smem[];
    const uint32_t sbase = smem_u32(smem);

    const int b    = blockIdx.z;
    const int h    = blockIdx.y;
    const int kvh  = h >> 2;
    const int tid  = threadIdx.x;
    const int lane = tid & 31;
    const int w    = tid >> 5;
    const int qrow = blockIdx.x * 128 + w * 16;

    uint32_t qf[2][4][4];
    {
        const size_t base = ((size_t)(b * S_ + qrow + (lane >> 2))) * DMODEL + h * HD + (lane & 3) * 2;
        #pragma unroll
        for (int kt = 0; kt < 4; kt++) {
            const size_t c = base + kt * 16;
            qf[0][kt][0] = *(const uint32_t*)(Qh + c);
            qf[0][kt][1] = *(const uint32_t*)(Qh + c + 8 * DMODEL);
            qf[0][kt][2] = *(const uint32_t*)(Qh + c + 8);
            qf[0][kt][3] = *(const uint32_t*)(Qh + c + 8 * DMODEL + 8);
            qf[1][kt][0] = *(const uint32_t*)(Ql + c);
            qf[1][kt][1] = *(const uint32_t*)(Ql + c + 8 * DMODEL);
            qf[1][kt][2] = *(const uint32_t*)(Ql + c + 8);
            qf[1][kt][3] = *(const uint32_t*)(Ql + c + 8 * DMODEL + 8);
        }
    }

    float o[8][4];
    #pragma unroll
    for (int nt = 0; nt < 8; nt++)
        #pragma unroll
        for (int r = 0; r < 4; r++) o[nt][r] = 0.0f;
    float m0 = -1e30f, m1 = -1e30f, l0 = 0.0f, l1 = 0.0f;

    const size_t kvbase = (size_t)b * S_ * KVD2 + kvh * HD;
    const __nv_bfloat16* gsrc[4] = {
        KVh + kvbase, KVl + kvbase,
        KVh + kvbase + KVDIM, KVl + kvbase + KVDIM };
    const int lrow = tid >> 2;
    const int lc   = tid & 3;

    auto load_tiles = [&](int buf, int lt) {
        #pragma unroll
        for (int t = 0; t < 4; t++) {
            const __nv_bfloat16* src = gsrc[t] + (size_t)(lt * 64 + lrow) * KVD2;
            uint32_t dbase = sbase + buf * ATT_BUF_BYTES + t * ATT_TILE_BYTES;
            cp16(dbase + SW(lrow * 128 + lc * 16), src + lc * 8);
            cp16(dbase + SW(lrow * 128 + (lc + 4) * 16), src + (lc + 4) * 8);
        }
    };

    load_tiles(0, 0);
    asm volatile("cp.async.commit_group;\n");

    const int l15 = lane & 15;
    const int colh = (lane >> 4) << 4;                       // k-half for non-trans x4
    const int r8 = (((lane >> 3) & 1) << 3) + (lane & 7);    // row-within-16 for trans x4
    const int cpair = (lane >> 4) << 4;                      // col-pair select (bytes)

    for (int lt = 0; lt < S_ / 64; lt++) {
        const int cur = lt & 1;
        if (lt + 1 < S_ / 64) load_tiles(1 - cur, lt + 1);
        asm volatile("cp.async.commit_group;\n");
        asm volatile("cp.async.wait_group 1;\n");
        __syncthreads();

        const uint32_t tb = sbase + cur * ATT_BUF_BYTES;

        float s[8][4];
        #pragma unroll
        for (int nt = 0; nt < 8; nt++)
            #pragma unroll
            for (int r = 0; r < 4; r++) s[nt][r] = 0.0f;

        // ---- S = Q K^T (3-term), K fragments via x4 over nt pairs
        #pragma unroll
        for (int np = 0; np < 4; np++) {
            #pragma unroll
            for (int kt = 0; kt < 4; kt++) {
                const uint32_t inner = (uint32_t)((np * 16 + l15) * 128 + kt * 32 + colh);
                uint32_t th[4], tl[4];
                ldsm_x4(th, tb + 0 * ATT_TILE_BYTES + SW(inner));
                ldsm_x4(tl, tb + 1 * ATT_TILE_BYTES + SW(inner));
                mma2(s[2*np],   qf[0][kt], th[0], th[2]);
                mma2(s[2*np+1], qf[0][kt], th[1], th[3]);
                mma2(s[2*np],   qf[0][kt], tl[0], tl[2]);
                mma2(s[2*np+1], qf[0][kt], tl[1], tl[3]);
                mma2(s[2*np],   qf[1][kt], th[0], th[2]);
                mma2(s[2*np+1], qf[1][kt], th[1], th[3]);
            }
        }

        float mx0 = -1e30f, mx1 = -1e30f;
        #pragma unroll
        for (int nt = 0; nt < 8; nt++) {
            mx0 = fmaxf(mx0, fmaxf(s[nt][0], s[nt][1]));
            mx1 = fmaxf(mx1, fmaxf(s[nt][2], s[nt][3]));
        }
        mx0 = fmaxf(mx0, __shfl_xor_sync(0xffffffffu, mx0, 1));
        mx0 = fmaxf(mx0, __shfl_xor_sync(0xffffffffu, mx0, 2));
        mx1 = fmaxf(mx1, __shfl_xor_sync(0xffffffffu, mx1, 1));
        mx1 = fmaxf(mx1, __shfl_xor_sync(0xffffffffu, mx1, 2));
        const float mn0 = fmaxf(m0, mx0), mn1 = fmaxf(m1, mx1);
        const float sc0 = fexp2(m0 - mn0), sc1 = fexp2(m1 - mn1);
        m0 = mn0; m1 = mn1;
        l0 *= sc0; l1 *= sc1;
        #pragma unroll
        for (int nt = 0; nt < 8; nt++) {
            o[nt][0] *= sc0; o[nt][1] *= sc0; o[nt][2] *= sc1; o[nt][3] *= sc1;
        }
        #pragma unroll
        for (int nt = 0; nt < 8; nt++) {
            float p0 = fexp2(s[nt][0] - m0), p1 = fexp2(s[nt][1] - m0);
            float p2 = fexp2(s[nt][2] - m1), p3 = fexp2(s[nt][3] - m1);
            l0 += p0 + p1; l1 += p2 + p3;
            s[nt][0] = p0; s[nt][1] = p1; s[nt][2] = p2; s[nt][3] = p3;
        }

        uint32_t ph_[4][4], pl_[4][4];
        #pragma unroll
        for (int lk = 0; lk < 4; lk++) {
            ph_[lk][0] = packsplit(s[2*lk][0],   s[2*lk][1],   pl_[lk][0]);
            ph_[lk][1] = packsplit(s[2*lk][2],   s[2*lk][3],   pl_[lk][1]);
            ph_[lk][2] = packsplit(s[2*lk+1][0], s[2*lk+1][1], pl_[lk][2]);
            ph_[lk][3] = packsplit(s[2*lk+1][2], s[2*lk+1][3], pl_[lk][3]);
        }

        // ---- O += P V (3-term), V fragments via trans x4 over col pairs
        #pragma unroll
        for (int ntp = 0; ntp < 4; ntp++) {
            #pragma unroll
            for (int lk = 0; lk < 4; lk++) {
                const uint32_t inner = (uint32_t)((lk * 16 + r8) * 128 + ntp * 32 + cpair);
                uint32_t vh[4], vl[4];
                ldsm_x4_t(vh, tb + 2 * ATT_TILE_BYTES + SW(inner));
                ldsm_x4_t(vl, tb + 3 * ATT_TILE_BYTES + SW(inner));
                mma2(o[2*ntp],   ph_[lk], vh[0], vh[1]);
                mma2(o[2*ntp+1], ph_[lk], vh[2], vh[3]);
                mma2(o[2*ntp],   ph_[lk], vl[0], vl[1]);
                mma2(o[2*ntp+1], ph_[lk], vl[2], vl[3]);
                mma2(o[2*ntp],   pl_[lk], vh[0], vh[1]);
                mma2(o[2*ntp+1], pl_[lk], vh[2], vh[3]);
            }
        }
        __syncthreads();
    }

    l0 += __shfl_xor_sync(0xffffffffu, l0, 1);
    l0 += __shfl_xor_sync(0xffffffffu, l0, 2);
    l1 += __shfl_xor_sync(0xffffffffu, l1, 1);
    l1 += __shfl_xor_sync(0xffffffffu, l1, 2);
    const float inv0 = 1.0f / l0, inv1 = 1.0f / l1;

    const size_t ro = ((size_t)(b * S_ + qrow + (lane >> 2))) * DMODEL + h * HD + (lane & 3) * 2;
    #pragma unroll
    for (int nt = 0; nt < 8; nt++) {
        uint32_t lo0, lo1;
        uint32_t hi0 = packsplit(o[nt][0] * inv0, o[nt][1] * inv0, lo0);
        uint32_t hi1 = packsplit(o[nt][2] * inv1, o[nt][3] * inv1, lo1);
        *(uint32_t*)(AOh + ro + nt * 8)              = hi0;
        *(uint32_t*)(AOl + ro + nt * 8)              = lo0;
        *(uint32_t*)(AOh + ro + nt * 8 + 8 * DMODEL) = hi1;
        *(uint32_t*)(AOl + ro + nt * 8 + 8 * DMODEL) = lo1;
    }
}

// ---------------------------------------------------------------------------
// Launch
// ---------------------------------------------------------------------------
extern "C" void kernel_launch(void* const* d_in, const int* in_sizes, int n_in,
                              void* d_out, int out_size)
{
    const float* h_bsd = (const float*)d_in[0];
    const float* w_q   = (const float*)d_in[1];
    const float* w_k   = (const float*)d_in[2];
    const float* w_v   = (const float*)d_in[3];
    const float* w_o   = (const float*)d_in[4];
    float* out = (float*)d_out;

    __nv_bfloat16 *Xh, *Xl, *Wqh, *Wql, *Wkvh, *Wkvl, *Woh, *Wol;
    __nv_bfloat16 *Qh, *Ql, *KVh, *KVl, *AOh, *AOl;
    cudaGetSymbolAddress((void**)&Xh, g_Xh);   cudaGetSymbolAddress((void**)&Xl, g_Xl);
    cudaGetSymbolAddress((void**)&Wqh, g_Wqh); cudaGetSymbolAddress((void**)&Wql, g_Wql);
    cudaGetSymbolAddress((void**)&Wkvh, g_Wkvh); cudaGetSymbolAddress((void**)&Wkvl, g_Wkvl);
    cudaGetSymbolAddress((void**)&Woh, g_Woh); cudaGetSymbolAddress((void**)&Wol, g_Wol);
    cudaGetSymbolAddress((void**)&Qh, g_Qh);   cudaGetSymbolAddress((void**)&Ql, g_Ql);
    cudaGetSymbolAddress((void**)&KVh, g_KVh); cudaGetSymbolAddress((void**)&KVl, g_KVl);
    cudaGetSymbolAddress((void**)&AOh, g_AOh); cudaGetSymbolAddress((void**)&AOl, g_AOl);

    static int attr_set = 0;
    if (!attr_set) {
        cudaFuncSetAttribute(flash_attn_mma,
                             cudaFuncAttributeMaxDynamicSharedMemorySize, ATT_SMEM);
        cudaFuncSetAttribute(gemm_split,
                             cudaFuncAttributeMaxDynamicSharedMemorySize, GEMM_SMEM);
        attr_set = 1;
    }

    const int CV = 256;
    split2_bf16<<<512, CV>>>(h_bsd, Xh, Xl, MROWS * DMODEL / 4);
    split2_bf16<<<512, CV>>>(w_q, Wqh, Wql, DMODEL * DMODEL / 4);
    split2_bf16<<<256, CV>>>(w_k, Wkvh, Wkvl, KVDIM * DMODEL / 4);
    split2_bf16<<<256, CV>>>(w_v, Wkvh + (size_t)KVDIM * DMODEL,
                             Wkvl + (size_t)KVDIM * DMODEL, KVDIM * DMODEL / 4);
    split2_bf16<<<512, CV>>>(w_o, Woh, Wol, DMODEL * DMODEL / 4);

    gemm_split<<<dim3(DMODEL / TCN, MROWS / TCM), 512, GEMM_SMEM>>>(
        Xh, Xl, Wqh, Wql, nullptr, Qh, Ql, QSCALE, MROWS, DMODEL, DMODEL);
    gemm_split<<<dim3(KVD2 / TCN, MROWS / TCM), 512, GEMM_SMEM>>>(
        Xh, Xl, Wkvh, Wkvl, nullptr, KVh, KVl, 1.0f, MROWS, KVD2, DMODEL);

    flash_attn_mma<<<dim3(S_ / 128, NQH, B_), 256, ATT_SMEM>>>(
        Qh, Ql, KVh, KVl, AOh, AOl);

    gemm_split<<<dim3(DMODEL / TCN, MROWS / TCM), 512, GEMM_SMEM>>>(
        AOh, AOl, Woh, Wol, out, nullptr, nullptr, 1.0f, MROWS, DMODEL, DMODEL);
}

// round 13
// speedup vs baseline: 4.8962x; 1.4422x over previous
#include <cuda_runtime.h>
#include <cuda_fp16.h>
#include <math.h>
#include <stdint.h>

// Problem constants
#define B_      2
#define S_      2048
#define DMODEL  2048
#define NQH     32
#define NKVH    8
#define HD      64
#define KVDIM   (NKVH * HD)   // 512
#define KVD2    (2 * KVDIM)   // 1024 (K and V fused)
#define MROWS   (B_ * S_)     // 4096
#define NQW     (DMODEL * DMODEL)   // wq / wo element count
#define NKW     (KVDIM * DMODEL)    // wk / wv element count

// ---------------------------------------------------------------------------
// Scratch (__device__ globals; no allocation allowed)
// W layout: [Wq | Wk | Wv | Wo] fp16 (hi-only; B-side of all GEMMs)
// ---------------------------------------------------------------------------
__device__ __half g_W  [2 * NQW + 2 * NKW];          // 20 MB
__device__ __half g_Xh [MROWS * DMODEL], g_Xl [MROWS * DMODEL];
__device__ __half g_Qh [MROWS * DMODEL], g_Ql [MROWS * DMODEL];
__device__ __half g_KVh[MROWS * KVD2];
__device__ __half g_AOh[MROWS * DMODEL], g_AOl[MROWS * DMODEL];

// ---------------------------------------------------------------------------
// helpers
// ---------------------------------------------------------------------------
__device__ __forceinline__ uint32_t smem_u32(const void* p) {
    return (uint32_t)__cvta_generic_to_shared(p);
}

// fp16 2-way split: returns packed hi pair, writes packed lo pair
__device__ __forceinline__ uint32_t packsplit_h(float a, float b, uint32_t& lo) {
    __half ha = __float2half_rn(a), hb = __float2half_rn(b);
    __half la = __float2half_rn(a - __half2float(ha));
    __half lb = __float2half_rn(b - __half2float(hb));
    lo = ((uint32_t)__half_as_ushort(lb) << 16) | (uint32_t)__half_as_ushort(la);
    return ((uint32_t)__half_as_ushort(hb) << 16) | (uint32_t)__half_as_ushort(ha);
}

__device__ __forceinline__ float fexp2(float x) {
    float r;
    asm("ex2.approx.f32 %0, %1;" : "=f"(r) : "f"(x));
    return r;
}

// fp16 mma, b-operand as two explicit regs
__device__ __forceinline__ void mma2(float* c, const uint32_t* a, uint32_t b0, uint32_t b1) {
    asm volatile(
        "mma.sync.aligned.m16n8k16.row.col.f32.f16.f16.f32 "
        "{%0,%1,%2,%3}, {%4,%5,%6,%7}, {%8,%9}, {%0,%1,%2,%3};"
        : "+f"(c[0]), "+f"(c[1]), "+f"(c[2]), "+f"(c[3])
        : "r"(a[0]), "r"(a[1]), "r"(a[2]), "r"(a[3]), "r"(b0), "r"(b1));
}

__device__ __forceinline__ void ldsm_x4(uint32_t* r, uint32_t addr) {
    asm volatile("ldmatrix.sync.aligned.m8n8.x4.shared.b16 {%0,%1,%2,%3}, [%4];"
                 : "=r"(r[0]), "=r"(r[1]), "=r"(r[2]), "=r"(r[3]) : "r"(addr));
}
__device__ __forceinline__ void ldsm_x4_t(uint32_t* r, uint32_t addr) {
    asm volatile("ldmatrix.sync.aligned.m8n8.x4.trans.shared.b16 {%0,%1,%2,%3}, [%4];"
                 : "=r"(r[0]), "=r"(r[1]), "=r"(r[2]), "=r"(r[3]) : "r"(addr));
}

#define SW(a) ((a) ^ (((a) >> 3) & 0x70))

__device__ __forceinline__ void cp16(uint32_t d, const void* s) {
    asm volatile("cp.async.cg.shared.global [%0], [%1], 16;\n" :: "r"(d), "l"(s));
}

// softmax scale: 1/sqrt(64) * log2(e)
#define QSCALE 0.18033688011112042f

// ---------------------------------------------------------------------------
// Weight convert (hi-only fp16) into packed g_W: [Wq | Wk | Wv | Wo]
// ---------------------------------------------------------------------------
__global__ void cvt_w4(const float* __restrict__ wq, const float* __restrict__ wk,
                       const float* __restrict__ wv, const float* __restrict__ wo,
                       __half* __restrict__ W)
{
    const int total2 = (2 * NQW + 2 * NKW) / 2;
    for (int i = blockIdx.x * blockDim.x + threadIdx.x; i < total2;
         i += gridDim.x * blockDim.x) {
        const int idx = i * 2;
        const float* src; int off;
        if (idx < NQW)                 { src = wq; off = idx; }
        else if (idx < NQW + NKW)      { src = wk; off = idx - NQW; }
        else if (idx < NQW + 2 * NKW)  { src = wv; off = idx - NQW - NKW; }
        else                           { src = wo; off = idx - NQW - 2 * NKW; }
        float2 v = *(const float2*)(src + off);
        __half2 h; h.x = __float2half_rn(v.x); h.y = __float2half_rn(v.y);
        *(__half2*)(W + idx) = h;
    }
}

// ---------------------------------------------------------------------------
// X: fp32 -> (hi, lo) fp16 buffers.
// ---------------------------------------------------------------------------
__global__ void split2_f16(const float* __restrict__ X,
                           __half* __restrict__ Yh, __half* __restrict__ Yl, int total4)
{
    for (int i = blockIdx.x * blockDim.x + threadIdx.x; i < total4;
         i += gridDim.x * blockDim.x) {
        const int idx = i * 4;
        float4 x = *(const float4*)(X + idx);
        uint32_t lo0, lo1;
        uint32_t hi0 = packsplit_h(x.x, x.y, lo0);
        uint32_t hi1 = packsplit_h(x.z, x.w, lo1);
        *(uint2*)(Yh + idx) = make_uint2(hi0, hi1);
        *(uint2*)(Yl + idx) = make_uint2(lo0, lo1);
    }
}

// ---------------------------------------------------------------------------
// Split-precision GEMM on fp16 mma.sync:
//   C[M,N] = (Ah+Al)[M,K] * Bh[N,K]^T   (2 terms: AhBh + AlBh)
// CTA 128x256, 16 warps (4M x 4N) at 32x64 each, TCK=64, SW128 stages, 2-stage.
// Output: fp32 C, or 2-term fp16 (Chi+Clo), or 1-term fp16 (Chi only).
// ---------------------------------------------------------------------------
#define TCM 128
#define TCN 256
#define TCK 64
// per-stage (bytes): Ah 16K | Al 16K | Bh 32K
#define GA_AL 16384
#define GA_BH 32768
#define STAGE_BYTES 65536
#define GEMM_SMEM (2 * STAGE_BYTES)    // 131072

__global__ void __launch_bounds__(512, 1) gemm_split(
    const __half* __restrict__ Ah, const __half* __restrict__ Al,
    const __half* __restrict__ Bh,
    float* __restrict__ C,
    __half* __restrict__ Chi, __half* __restrict__ Clo,
    float cscale, int M, int N, int Kk)
{
    extern __shared__ __align__(1024) char sm[];
    const uint32_t sb = smem_u32(sm);

    const int tid  = threadIdx.x;
    const int lane = tid & 31;
    const int w    = tid >> 5;          // 0..15
    const int wm   = (w & 3) * 32;      // M slab (4 x 32)
    const int wn   = (w >> 2) * 64;     // N slab (4 x 64)
    const int bm   = blockIdx.y * TCM;
    const int bn   = blockIdx.x * TCN;

    float acc[2][8][4];
    #pragma unroll
    for (int mi = 0; mi < 2; mi++)
        #pragma unroll
        for (int nt = 0; nt < 8; nt++)
            #pragma unroll
            for (int r = 0; r < 4; r++) acc[mi][nt][r] = 0.0f;

    // load mapping (512 threads, 128B rows = 8 x 16B chunks):
    const int arow = tid >> 2, ach = (tid & 3) * 2;
    const int brow = tid >> 1, bch = (tid & 1) * 4;
    const __half* gAh = Ah + (size_t)(bm + arow) * Kk + ach * 8;
    const __half* gAl = Al + (size_t)(bm + arow) * Kk + ach * 8;
    const __half* gBh = Bh + (size_t)(bn + brow) * Kk + bch * 8;

    auto load_stage = [&](int buf, int kt) {
        const uint32_t st = sb + buf * STAGE_BYTES;
        const int k0 = kt * TCK;
        #pragma unroll
        for (int j = 0; j < 2; j++) {
            const uint32_t d = SW((uint32_t)(arow * 128 + (ach + j) * 16));
            cp16(st + d, gAh + k0 + j * 8);
            cp16(st + GA_AL + d, gAl + k0 + j * 8);
        }
        #pragma unroll
        for (int j = 0; j < 4; j++) {
            const uint32_t d = SW((uint32_t)(brow * 128 + (bch + j) * 16));
            cp16(st + GA_BH + d, gBh + k0 + j * 8);
        }
    };

    const int NT = Kk / TCK;
    load_stage(0, 0);
    asm volatile("cp.async.commit_group;\n");

    const int l15 = lane & 15;
    const int colh = (lane >> 4) << 4;   // 0 or 16 bytes (k-half)

    for (int kt = 0; kt < NT; kt++) {
        const int cur = kt & 1;
        if (kt + 1 < NT) {
            load_stage(1 - cur, kt + 1);
            asm volatile("cp.async.commit_group;\n");
            asm volatile("cp.async.wait_group 1;\n");
        } else {
            asm volatile("cp.async.wait_group 0;\n");
        }
        __syncthreads();

        const uint32_t st = sb + cur * STAGE_BYTES;

        #pragma unroll
        for (int kk = 0; kk < 4; kk++) {            // 4 x k16
            const uint32_t colb = (uint32_t)(kk * 32 + colh);
            uint32_t ah[2][4], al[2][4];
            #pragma unroll
            for (int mi = 0; mi < 2; mi++) {
                const uint32_t off = SW((uint32_t)((wm + mi * 16 + l15) * 128) + colb);
                ldsm_x4(ah[mi], st + off);
                ldsm_x4(al[mi], st + GA_AL + off);
            }
            #pragma unroll
            for (int np = 0; np < 4; np++) {
                const uint32_t offb = SW((uint32_t)((wn + np * 16 + l15) * 128) + colb);
                uint32_t t[4];
                ldsm_x4(t, st + GA_BH + offb);
                mma2(acc[0][2*np],   ah[0], t[0], t[2]);
                mma2(acc[0][2*np+1], ah[0], t[1], t[3]);
                mma2(acc[1][2*np],   ah[1], t[0], t[2]);
                mma2(acc[1][2*np+1], ah[1], t[1], t[3]);
                mma2(acc[0][2*np],   al[0], t[0], t[2]);
                mma2(acc[0][2*np+1], al[0], t[1], t[3]);
                mma2(acc[1][2*np],   al[1], t[0], t[2]);
                mma2(acc[1][2*np+1], al[1], t[1], t[3]);
            }
        }
        __syncthreads();
    }

    // ---- epilogue: fp32 / 2-term fp16 / 1-term fp16
    if (C) {
        #pragma unroll
        for (int mi = 0; mi < 2; mi++) {
            const int r0 = bm + wm + mi * 16 + (lane >> 2);
            #pragma unroll
            for (int nt = 0; nt < 8; nt++) {
                const int c0 = bn + wn + nt * 8 + 2 * (lane & 3);
                *(float2*)(C + (size_t)r0 * N + c0)       = make_float2(acc[mi][nt][0], acc[mi][nt][1]);
                *(float2*)(C + (size_t)(r0 + 8) * N + c0) = make_float2(acc[mi][nt][2], acc[mi][nt][3]);
            }
        }
    } else if (Clo) {
        #pragma unroll
        for (int mi = 0; mi < 2; mi++) {
            const int r0 = bm + wm + mi * 16 + (lane >> 2);
            #pragma unroll
            for (int nt = 0; nt < 8; nt++) {
                const int c0 = bn + wn + nt * 8 + 2 * (lane & 3);
                uint32_t lo0, lo1;
                uint32_t hi0 = packsplit_h(acc[mi][nt][0] * cscale, acc[mi][nt][1] * cscale, lo0);
                uint32_t hi1 = packsplit_h(acc[mi][nt][2] * cscale, acc[mi][nt][3] * cscale, lo1);
                *(uint32_t*)(Chi + (size_t)r0 * N + c0)       = hi0;
                *(uint32_t*)(Clo + (size_t)r0 * N + c0)       = lo0;
                *(uint32_t*)(Chi + (size_t)(r0 + 8) * N + c0) = hi1;
                *(uint32_t*)(Clo + (size_t)(r0 + 8) * N + c0) = lo1;
            }
        }
    } else {
        #pragma unroll
        for (int mi = 0; mi < 2; mi++) {
            const int r0 = bm + wm + mi * 16 + (lane >> 2);
            #pragma unroll
            for (int nt = 0; nt < 8; nt++) {
                const int c0 = bn + wn + nt * 8 + 2 * (lane & 3);
                __half2 h0, h1;
                h0.x = __float2half_rn(acc[mi][nt][0]); h0.y = __float2half_rn(acc[mi][nt][1]);
                h1.x = __float2half_rn(acc[mi][nt][2]); h1.y = __float2half_rn(acc[mi][nt][3]);
                *(__half2*)(Chi + (size_t)r0 * N + c0)       = h0;
                *(__half2*)(Chi + (size_t)(r0 + 8) * N + c0) = h1;
            }
        }
    }
}

// ---------------------------------------------------------------------------
// fp16 flash attention: S = (Qh+Ql)Kh^T, O += (Ph+Pl)Vh, log2-domain softmax.
// K/V hi-only tiles -> 16KB/buffer, 32KB total smem.
// ---------------------------------------------------------------------------
#define ATT_TILE_BYTES 8192
#define ATT_BUF_BYTES  (2 * ATT_TILE_BYTES)
#define ATT_SMEM       (2 * ATT_BUF_BYTES)   // 32768

__global__ void __launch_bounds__(256) flash_attn_mma(
    const __half* __restrict__ Qh, const __half* __restrict__ Ql,
    const __half* __restrict__ KVh,
    __half* __restrict__ AOh, __half* __restrict__ AOl)
{
    extern __shared__ __half smem[];
    const uint32_t sbase = smem_u32(smem);

    const int b    = blockIdx.z;
    const int h    = blockIdx.y;
    const int kvh  = h >> 2;
    const int tid  = threadIdx.x;
    const int lane = tid & 31;
    const int w    = tid >> 5;
    const int qrow = blockIdx.x * 128 + w * 16;

    uint32_t qf[2][4][4];
    {
        const size_t base = ((size_t)(b * S_ + qrow + (lane >> 2))) * DMODEL + h * HD + (lane & 3) * 2;
        #pragma unroll
        for (int kt = 0; kt < 4; kt++) {
            const size_t c = base + kt * 16;
            qf[0][kt][0] = *(const uint32_t*)(Qh + c);
            qf[0][kt][1] = *(const uint32_t*)(Qh + c + 8 * DMODEL);
            qf[0][kt][2] = *(const uint32_t*)(Qh + c + 8);
            qf[0][kt][3] = *(const uint32_t*)(Qh + c + 8 * DMODEL + 8);
            qf[1][kt][0] = *(const uint32_t*)(Ql + c);
            qf[1][kt][1] = *(const uint32_t*)(Ql + c + 8 * DMODEL);
            qf[1][kt][2] = *(const uint32_t*)(Ql + c + 8);
            qf[1][kt][3] = *(const uint32_t*)(Ql + c + 8 * DMODEL + 8);
        }
    }

    float o[8][4];
    #pragma unroll
    for (int nt = 0; nt < 8; nt++)
        #pragma unroll
        for (int r = 0; r < 4; r++) o[nt][r] = 0.0f;
    float m0 = -1e30f, m1 = -1e30f, l0 = 0.0f, l1 = 0.0f;

    const size_t kvbase = (size_t)b * S_ * KVD2 + kvh * HD;
    const __half* gK = KVh + kvbase;
    const __half* gV = KVh + kvbase + KVDIM;
    const int lrow = tid >> 2;
    const int lc   = tid & 3;

    auto load_tiles = [&](int buf, int lt) {
        const __half* srcK = gK + (size_t)(lt * 64 + lrow) * KVD2;
        const __half* srcV = gV + (size_t)(lt * 64 + lrow) * KVD2;
        uint32_t dK = sbase + buf * ATT_BUF_BYTES;
        uint32_t dV = dK + ATT_TILE_BYTES;
        cp16(dK + SW(lrow * 128 + lc * 16), srcK + lc * 8);
        cp16(dK + SW(lrow * 128 + (lc + 4) * 16), srcK + (lc + 4) * 8);
        cp16(dV + SW(lrow * 128 + lc * 16), srcV + lc * 8);
        cp16(dV + SW(lrow * 128 + (lc + 4) * 16), srcV + (lc + 4) * 8);
    };

    load_tiles(0, 0);
    asm volatile("cp.async.commit_group;\n");

    const int l15 = lane & 15;
    const int colh = (lane >> 4) << 4;                       // k-half for non-trans x4
    const int r8 = (((lane >> 3) & 1) << 3) + (lane & 7);    // row for trans x4
    const int cpair = (lane >> 4) << 4;                      // col-pair select (bytes)

    for (int lt = 0; lt < S_ / 64; lt++) {
        const int cur = lt & 1;
        if (lt + 1 < S_ / 64) load_tiles(1 - cur, lt + 1);
        asm volatile("cp.async.commit_group;\n");
        asm volatile("cp.async.wait_group 1;\n");
        __syncthreads();

        const uint32_t tbK = sbase + cur * ATT_BUF_BYTES;
        const uint32_t tbV = tbK + ATT_TILE_BYTES;

        float s[8][4];
        #pragma unroll
        for (int nt = 0; nt < 8; nt++)
            #pragma unroll
            for (int r = 0; r < 4; r++) s[nt][r] = 0.0f;

        // ---- S = (Qh+Ql) Kh^T
        #pragma unroll
        for (int np = 0; np < 4; np++) {
            #pragma unroll
            for (int kt = 0; kt < 4; kt++) {
                const uint32_t inner = (uint32_t)((np * 16 + l15) * 128 + kt * 32 + colh);
                uint32_t th[4];
                ldsm_x4(th, tbK + SW(inner));
                mma2(s[2*np],   qf[0][kt], th[0], th[2]);
                mma2(s[2*np+1], qf[0][kt], th[1], th[3]);
                mma2(s[2*np],   qf[1][kt], th[0], th[2]);
                mma2(s[2*np+1], qf[1][kt], th[1], th[3]);
            }
        }

        float mx0 = -1e30f, mx1 = -1e30f;
        #pragma unroll
        for (int nt = 0; nt < 8; nt++) {
            mx0 = fmaxf(mx0, fmaxf(s[nt][0], s[nt][1]));
            mx1 = fmaxf(mx1, fmaxf(s[nt][2], s[nt][3]));
        }
        mx0 = fmaxf(mx0, __shfl_xor_sync(0xffffffffu, mx0, 1));
        mx0 = fmaxf(mx0, __shfl_xor_sync(0xffffffffu, mx0, 2));
        mx1 = fmaxf(mx1, __shfl_xor_sync(0xffffffffu, mx1, 1));
        mx1 = fmaxf(mx1, __shfl_xor_sync(0xffffffffu, mx1, 2));
        const float mn0 = fmaxf(m0, mx0), mn1 = fmaxf(m1, mx1);
        const float sc0 = fexp2(m0 - mn0), sc1 = fexp2(m1 - mn1);
        m0 = mn0; m1 = mn1;
        l0 *= sc0; l1 *= sc1;
        #pragma unroll
        for (int nt = 0; nt < 8; nt++) {
            o[nt][0] *= sc0; o[nt][1] *= sc0; o[nt][2] *= sc1; o[nt][3] *= sc1;
        }
        #pragma unroll
        for (int nt = 0; nt < 8; nt++) {
            float p0 = fexp2(s[nt][0] - m0), p1 = fexp2(s[nt][1] - m0);
            float p2 = fexp2(s[nt][2] - m1), p3 = fexp2(s[nt][3] - m1);
            l0 += p0 + p1; l1 += p2 + p3;
            s[nt][0] = p0; s[nt][1] = p1; s[nt][2] = p2; s[nt][3] = p3;
        }

        uint32_t ph_[4][4], pl_[4][4];
        #pragma unroll
        for (int lk = 0; lk < 4; lk++) {
            ph_[lk][0] = packsplit_h(s[2*lk][0],   s[2*lk][1],   pl_[lk][0]);
            ph_[lk][1] = packsplit_h(s[2*lk][2],   s[2*lk][3],   pl_[lk][1]);
            ph_[lk][2] = packsplit_h(s[2*lk+1][0], s[2*lk+1][1], pl_[lk][2]);
            ph_[lk][3] = packsplit_h(s[2*lk+1][2], s[2*lk+1][3], pl_[lk][3]);
        }

        // ---- O += (Ph+Pl) Vh
        #pragma unroll
        for (int ntp = 0; ntp < 4; ntp++) {
            #pragma unroll
            for (int lk = 0; lk < 4; lk++) {
                const uint32_t inner = (uint32_t)((lk * 16 + r8) * 128 + ntp * 32 + cpair);
                uint32_t vh[4];
                ldsm_x4_t(vh, tbV + SW(inner));
                mma2(o[2*ntp],   ph_[lk], vh[0], vh[1]);
                mma2(o[2*ntp+1], ph_[lk], vh[2], vh[3]);
                mma2(o[2*ntp],   pl_[lk], vh[0], vh[1]);
                mma2(o[2*ntp+1], pl_[lk], vh[2], vh[3]);
            }
        }
        __syncthreads();
    }

    l0 += __shfl_xor_sync(0xffffffffu, l0, 1);
    l0 += __shfl_xor_sync(0xffffffffu, l0, 2);
    l1 += __shfl_xor_sync(0xffffffffu, l1, 1);
    l1 += __shfl_xor_sync(0xffffffffu, l1, 2);
    const float inv0 = 1.0f / l0, inv1 = 1.0f / l1;

    const size_t ro = ((size_t)(b * S_ + qrow + (lane >> 2))) * DMODEL + h * HD + (lane & 3) * 2;
    #pragma unroll
    for (int nt = 0; nt < 8; nt++) {
        uint32_t lo0, lo1;
        uint32_t hi0 = packsplit_h(o[nt][0] * inv0, o[nt][1] * inv0, lo0);
        uint32_t hi1 = packsplit_h(o[nt][2] * inv1, o[nt][3] * inv1, lo1);
        *(uint32_t*)(AOh + ro + nt * 8)              = hi0;
        *(uint32_t*)(AOl + ro + nt * 8)              = lo0;
        *(uint32_t*)(AOh + ro + nt * 8 + 8 * DMODEL) = hi1;
        *(uint32_t*)(AOl + ro + nt * 8 + 8 * DMODEL) = lo1;
    }
}

// ---------------------------------------------------------------------------
// Launch  (6 launches total; ncu -s 5 lands on a heavy kernel now)
// ---------------------------------------------------------------------------
extern "C" void kernel_launch(void* const* d_in, const int* in_sizes, int n_in,
                              void* d_out, int out_size)
{
    const float* h_bsd = (const float*)d_in[0];
    const float* w_q   = (const float*)d_in[1];
    const float* w_k   = (const float*)d_in[2];
    const float* w_v   = (const float*)d_in[3];
    const float* w_o   = (const float*)d_in[4];
    float* out = (float*)d_out;

    __half *W, *Xh, *Xl, *Qh, *Ql, *KVh, *AOh, *AOl;
    cudaGetSymbolAddress((void**)&W, g_W);
    cudaGetSymbolAddress((void**)&Xh, g_Xh);   cudaGetSymbolAddress((void**)&Xl, g_Xl);
    cudaGetSymbolAddress((void**)&Qh, g_Qh);   cudaGetSymbolAddress((void**)&Ql, g_Ql);
    cudaGetSymbolAddress((void**)&KVh, g_KVh);
    cudaGetSymbolAddress((void**)&AOh, g_AOh); cudaGetSymbolAddress((void**)&AOl, g_AOl);

    static int attr_set = 0;
    if (!attr_set) {
        cudaFuncSetAttribute(flash_attn_mma,
                             cudaFuncAttributeMaxDynamicSharedMemorySize, ATT_SMEM);
        cudaFuncSetAttribute(gemm_split,
                             cudaFuncAttributeMaxDynamicSharedMemorySize, GEMM_SMEM);
        attr_set = 1;
    }

    cvt_w4<<<512, 256>>>(w_q, w_k, w_v, w_o, W);
    split2_f16<<<512, 256>>>(h_bsd, Xh, Xl, MROWS * DMODEL / 4);

    // Q projection (scaled, 2-term fp16 out), fused KV projection (1-term out)
    gemm_split<<<dim3(DMODEL / TCN, MROWS / TCM), 512, GEMM_SMEM>>>(
        Xh, Xl, W, nullptr, Qh, Ql, QSCALE, MROWS, DMODEL, DMODEL);
    gemm_split<<<dim3(KVD2 / TCN, MROWS / TCM), 512, GEMM_SMEM>>>(
        Xh, Xl, W + NQW, nullptr, KVh, nullptr, 1.0f, MROWS, KVD2, DMODEL);

    flash_attn_mma<<<dim3(S_ / 128, NQH, B_), 256, ATT_SMEM>>>(
        Qh, Ql, KVh, AOh, AOl);

    gemm_split<<<dim3(DMODEL / TCN, MROWS / TCM), 512, GEMM_SMEM>>>(
        AOh, AOl, W + NQW + 2 * NKW, out, nullptr, nullptr, 1.0f, MROWS, DMODEL, DMODEL);
}